// round 3
// baseline (speedup 1.0000x reference)
#include <cuda_runtime.h>

#define BATCH 65536
#define NGRP  6
#define DIN   512
#define DF    256
#define NOUT  18

// ---------------- scratch (static device globals: no allocation) -------------
__device__ int   g_perm[BATCH];
__device__ int   g_off[NGRP + 1];
__device__ float g_h1[(size_t)BATCH * DF];   // 64 MB
__device__ float g_hf[(size_t)BATCH * DF];   // 64 MB

// ---------------- 1. stable counting sort of idx (1 block, 1024 thr) --------
__global__ void __launch_bounds__(1024) sort_kernel(const int* __restrict__ idx)
{
    __shared__ int s[NGRP][1024];
    __shared__ int s_base[NGRP + 1];
    const int t = threadIdx.x;
    const int per = BATCH / 1024;          // 64
    const int base = t * per;

    int cnt[NGRP];
#pragma unroll
    for (int g = 0; g < NGRP; g++) cnt[g] = 0;
    for (int i = 0; i < per; i++) {
        int v = idx[base + i];
#pragma unroll
        for (int g = 0; g < NGRP; g++) cnt[g] += (v == g);
    }
#pragma unroll
    for (int g = 0; g < NGRP; g++) s[g][t] = cnt[g];
    __syncthreads();

    // Hillis-Steele inclusive scan over the 1024 threads, 6 lanes at once
    for (int d = 1; d < 1024; d <<= 1) {
        int v[NGRP];
        if (t >= d) {
#pragma unroll
            for (int g = 0; g < NGRP; g++) v[g] = s[g][t - d];
        }
        __syncthreads();
        if (t >= d) {
#pragma unroll
            for (int g = 0; g < NGRP; g++) s[g][t] += v[g];
        }
        __syncthreads();
    }

    if (t == 0) {
        int acc = 0;
#pragma unroll
        for (int g = 0; g < NGRP; g++) { s_base[g] = acc; acc += s[g][1023]; }
        s_base[NGRP] = acc;
        for (int g = 0; g <= NGRP; g++) g_off[g] = s_base[g];
    }
    __syncthreads();

    int pos[NGRP];
#pragma unroll
    for (int g = 0; g < NGRP; g++) pos[g] = s_base[g] + s[g][t] - cnt[g];

    for (int i = 0; i < per; i++) {
        int v = idx[base + i];
        int p = 0;
#pragma unroll
        for (int g = 0; g < NGRP; g++) if (v == g) p = pos[g]++;
        g_perm[p] = base + i;
    }
}

// ---------------- 2. GEMM1: h1 = sigmoid(state[perm] @ W1[g]) ---------------
// tile 128x128, K-chunk 16, 256 threads, 8x8 per thread
__global__ void __launch_bounds__(256) gemm1_kernel(
    const float* __restrict__ state, const float* __restrict__ W1,
    const float* __restrict__ b1)
{
    const int g = blockIdx.y;
    const int row_start = g_off[g] + blockIdx.x * 128;
    const int row_end   = g_off[g + 1];
    if (row_start >= row_end) return;
    const int n0 = blockIdx.z * 128;
    const float* Wg = W1 + (size_t)g * DIN * DF;

    __shared__ float As[16][128];
    __shared__ float Bs[16][128];

    const int tid = threadIdx.x;
    const int tx = tid & 15, ty = tid >> 4;

    // A loaders: 512 float4 per chunk (128 rows x 4)
    const int f0 = tid, f1 = tid + 256;
    const int ar0 = f0 >> 2, ak0 = (f0 & 3) * 4;
    const int ar1 = f1 >> 2, ak1 = (f1 & 3) * 4;
    const int m0 = row_start + ar0, m1 = row_start + ar1;
    const float* src0 = (m0 < row_end) ? state + (size_t)g_perm[m0] * DIN : nullptr;
    const float* src1 = (m1 < row_end) ? state + (size_t)g_perm[m1] * DIN : nullptr;
    // B loaders: 512 float4 per chunk (16 rows x 32)
    const int br0 = tid >> 5;            // 0..7
    const int br1 = br0 + 8;             // 8..15
    const int bc  = (tid & 31) * 4;

    float acc[8][8];
#pragma unroll
    for (int i = 0; i < 8; i++)
#pragma unroll
        for (int j = 0; j < 8; j++) acc[i][j] = 0.f;

    const float4 z4 = make_float4(0.f, 0.f, 0.f, 0.f);
    float4 av0 = src0 ? *(const float4*)(src0 + ak0) : z4;
    float4 av1 = src1 ? *(const float4*)(src1 + ak1) : z4;
    float4 bv0 = *(const float4*)(Wg + (size_t)br0 * DF + n0 + bc);
    float4 bv1 = *(const float4*)(Wg + (size_t)br1 * DF + n0 + bc);

    for (int k0 = 0; k0 < DIN; k0 += 16) {
        __syncthreads();
        As[ak0 + 0][ar0] = av0.x; As[ak0 + 1][ar0] = av0.y;
        As[ak0 + 2][ar0] = av0.z; As[ak0 + 3][ar0] = av0.w;
        As[ak1 + 0][ar1] = av1.x; As[ak1 + 1][ar1] = av1.y;
        As[ak1 + 2][ar1] = av1.z; As[ak1 + 3][ar1] = av1.w;
        *(float4*)&Bs[br0][bc] = bv0;
        *(float4*)&Bs[br1][bc] = bv1;
        __syncthreads();

        const int kn = k0 + 16;
        if (kn < DIN) {   // prefetch next chunk
            av0 = src0 ? *(const float4*)(src0 + kn + ak0) : z4;
            av1 = src1 ? *(const float4*)(src1 + kn + ak1) : z4;
            bv0 = *(const float4*)(Wg + (size_t)(kn + br0) * DF + n0 + bc);
            bv1 = *(const float4*)(Wg + (size_t)(kn + br1) * DF + n0 + bc);
        }

#pragma unroll
        for (int kk = 0; kk < 16; kk++) {
            float a[8], b[8];
            *(float4*)(a)     = *(float4*)&As[kk][ty * 8];
            *(float4*)(a + 4) = *(float4*)&As[kk][ty * 8 + 4];
            *(float4*)(b)     = *(float4*)&Bs[kk][tx * 8];
            *(float4*)(b + 4) = *(float4*)&Bs[kk][tx * 8 + 4];
#pragma unroll
            for (int i = 0; i < 8; i++)
#pragma unroll
                for (int j = 0; j < 8; j++) acc[i][j] += a[i] * b[j];
        }
    }

#pragma unroll
    for (int i = 0; i < 8; i++) {
        const int m = row_start + ty * 8 + i;
        if (m < row_end) {
#pragma unroll
            for (int j = 0; j < 8; j++) {
                const int n = n0 + tx * 8 + j;
                float v = acc[i][j] + b1[g * DF + n];
                v = 1.f / (1.f + expf(-v));
                g_h1[(size_t)m * DF + n] = v;
            }
        }
    }
}

// ---------------- 3. GEMM2: hf = relu(h1 @ W2) ------------------------------
__global__ void __launch_bounds__(256) gemm2_kernel(
    const float* __restrict__ W2, const float* __restrict__ b2)
{
    const int row0 = blockIdx.x * 128;       // BATCH % 128 == 0, full tiles
    const int n0 = blockIdx.y * 128;

    __shared__ float As[16][128];
    __shared__ float Bs[16][128];

    const int tid = threadIdx.x;
    const int tx = tid & 15, ty = tid >> 4;

    const int ar0 = tid >> 2,        ak0 = (tid & 3) * 4;
    const int ar1 = (tid + 256) >> 2, ak1 = ak0;
    const float* srcA0 = g_h1 + (size_t)(row0 + ar0) * DF + ak0;
    const float* srcA1 = g_h1 + (size_t)(row0 + ar1) * DF + ak1;
    const int br0 = tid >> 5, br1 = br0 + 8;
    const int bc  = (tid & 31) * 4;

    float acc[8][8];
#pragma unroll
    for (int i = 0; i < 8; i++)
#pragma unroll
        for (int j = 0; j < 8; j++) acc[i][j] = 0.f;

    float4 av0 = *(const float4*)(srcA0);
    float4 av1 = *(const float4*)(srcA1);
    float4 bv0 = *(const float4*)(W2 + (size_t)br0 * DF + n0 + bc);
    float4 bv1 = *(const float4*)(W2 + (size_t)br1 * DF + n0 + bc);

    for (int k0 = 0; k0 < DF; k0 += 16) {
        __syncthreads();
        As[ak0 + 0][ar0] = av0.x; As[ak0 + 1][ar0] = av0.y;
        As[ak0 + 2][ar0] = av0.z; As[ak0 + 3][ar0] = av0.w;
        As[ak1 + 0][ar1] = av1.x; As[ak1 + 1][ar1] = av1.y;
        As[ak1 + 2][ar1] = av1.z; As[ak1 + 3][ar1] = av1.w;
        *(float4*)&Bs[br0][bc] = bv0;
        *(float4*)&Bs[br1][bc] = bv1;
        __syncthreads();

        const int kn = k0 + 16;
        if (kn < DF) {
            av0 = *(const float4*)(srcA0 + kn);
            av1 = *(const float4*)(srcA1 + kn);
            bv0 = *(const float4*)(W2 + (size_t)(kn + br0) * DF + n0 + bc);
            bv1 = *(const float4*)(W2 + (size_t)(kn + br1) * DF + n0 + bc);
        }

#pragma unroll
        for (int kk = 0; kk < 16; kk++) {
            float a[8], b[8];
            *(float4*)(a)     = *(float4*)&As[kk][ty * 8];
            *(float4*)(a + 4) = *(float4*)&As[kk][ty * 8 + 4];
            *(float4*)(b)     = *(float4*)&Bs[kk][tx * 8];
            *(float4*)(b + 4) = *(float4*)&Bs[kk][tx * 8 + 4];
#pragma unroll
            for (int i = 0; i < 8; i++)
#pragma unroll
                for (int j = 0; j < 8; j++) acc[i][j] += a[i] * b[j];
        }
    }

#pragma unroll
    for (int i = 0; i < 8; i++) {
        const int m = row0 + ty * 8 + i;
#pragma unroll
        for (int j = 0; j < 8; j++) {
            const int n = n0 + tx * 8 + j;
            float v = acc[i][j] + b2[n];
            g_hf[(size_t)m * DF + n] = fmaxf(v, 0.f);
        }
    }
}

// ---------------- 4. output: tanh(hf . Wq[idx,:,action]) --------------------
__global__ void __launch_bounds__(256) out_kernel(
    const int* __restrict__ action, const int* __restrict__ idx,
    const float* __restrict__ Wq, const float* __restrict__ bq,
    float* __restrict__ out)
{
    const int b = (blockIdx.x * blockDim.x + threadIdx.x) >> 5;
    const int lane = threadIdx.x & 31;
    if (b >= BATCH) return;
    const int g = idx[b];
    const int a = action[b];
    const float* hf = g_hf + (size_t)b * DF;
    const float* wq = Wq + (size_t)g * DF * NOUT + a;
    float sum = 0.f;
#pragma unroll
    for (int f = lane; f < DF; f += 32)
        sum += hf[f] * wq[(size_t)f * NOUT];
#pragma unroll
    for (int s = 16; s; s >>= 1) sum += __shfl_xor_sync(0xFFFFFFFFu, sum, s);
    if (lane == 0) out[b] = tanhf(sum + bq[g * NOUT + a]);
}

// ---------------- launcher ---------------------------------------------------
extern "C" void kernel_launch(void* const* d_in, const int* in_sizes, int n_in,
                              void* d_out, int out_size)
{
    const float* state  = (const float*)d_in[0];
    const int*   action = (const int*)d_in[1];
    const int*   idx    = (const int*)d_in[2];
    const float* W1     = (const float*)d_in[3];
    const float* b1     = (const float*)d_in[4];
    const float* W2     = (const float*)d_in[5];
    const float* b2     = (const float*)d_in[6];
    const float* Wq     = (const float*)d_in[7];
    const float* bq     = (const float*)d_in[8];
    float* out = (float*)d_out;

    sort_kernel<<<1, 1024>>>(idx);
    gemm1_kernel<<<dim3(BATCH / 128, NGRP, DF / 128), 256>>>(state, W1, b1);
    gemm2_kernel<<<dim3(BATCH / 128, DF / 128), 256>>>(W2, b2);
    out_kernel<<<(BATCH * 32) / 256, 256>>>(action, idx, Wq, bq, out);
}

// round 6
// speedup vs baseline: 2.5270x; 2.5270x over previous
#include <cuda_runtime.h>
#include <cuda_bf16.h>
#include <cstdint>

#define BATCH 65536
#define NGRP  6
#define DIN   512
#define DF    256
#define NOUT  18

// ---------------- scratch (static device globals) ----------------------------
__device__ int g_perm[BATCH];
__device__ int g_off[NGRP + 1];
__device__ __nv_bfloat16 g_W1Th[NGRP * DF * DIN];   // [g][n][k] K-major hi
__device__ __nv_bfloat16 g_W1Tl[NGRP * DF * DIN];   // lo
__device__ __nv_bfloat16 g_W2Th[DF * DF];           // [n][k]
__device__ __nv_bfloat16 g_W2Tl[DF * DF];
__device__ __nv_bfloat16 g_h1h[(size_t)BATCH * DF]; // sorted-row order
__device__ __nv_bfloat16 g_h1l[(size_t)BATCH * DF];

// ---------------- helpers ----------------------------------------------------
__device__ __forceinline__ uint32_t smem_u32(const void* p) {
    uint32_t a;
    asm("{ .reg .u64 t; cvta.to.shared.u64 t, %1; cvt.u32.u64 %0, t; }" : "=r"(a) : "l"(p));
    return a;
}
#define SWZ(x) ((x) ^ (((x) >> 3) & 0x70))

__device__ __forceinline__ void ldsm4(uint32_t* r, uint32_t addr) {
    asm volatile("ldmatrix.sync.aligned.m8n8.x4.shared.b16 {%0,%1,%2,%3}, [%4];"
                 : "=r"(r[0]), "=r"(r[1]), "=r"(r[2]), "=r"(r[3]) : "r"(addr));
}
__device__ __forceinline__ void mma16816(float* d, const uint32_t* a, uint32_t b0, uint32_t b1) {
    asm volatile("mma.sync.aligned.m16n8k16.row.col.f32.bf16.bf16.f32 "
                 "{%0,%1,%2,%3}, {%4,%5,%6,%7}, {%8,%9}, {%0,%1,%2,%3};"
                 : "+f"(d[0]), "+f"(d[1]), "+f"(d[2]), "+f"(d[3])
                 : "r"(a[0]), "r"(a[1]), "r"(a[2]), "r"(a[3]), "r"(b0), "r"(b1));
}
__device__ __forceinline__ uint32_t pack_bf2(float a, float b) {
    __nv_bfloat162 t = __floats2bfloat162_rn(a, b);
    return *reinterpret_cast<uint32_t*>(&t);
}

// smem stage layout (bytes, relative to stage base)
#define OFF_AH 0        // 128 rows x 128B
#define OFF_AL 16384
#define OFF_BH 32768    // 256 rows x 128B
#define OFF_BL 65536
#define STAGE_B 98304
#define SMEM_TOTAL (2 * STAGE_B)

// stage B: 256 n-rows x 64 k bf16 (hi+lo) from pre-split K-major weights
__device__ __forceinline__ void stage_b(char* st, const __nv_bfloat16* srcH,
                                        const __nv_bfloat16* srcL, int k0, int ldk, int tid) {
    const int seg = tid & 7;
    const int rb = tid >> 3;
#pragma unroll
    for (int i = 0; i < 8; i++) {
        int r = rb + i * 32;
        size_t gofs = (size_t)r * ldk + k0 + seg * 8;
        uint4 vh = *(const uint4*)(srcH + gofs);
        uint4 vl = *(const uint4*)(srcL + gofs);
        uint32_t off = SWZ((uint32_t)(r * 128 + seg * 16));
        *(uint4*)(st + OFF_BH + off) = vh;
        *(uint4*)(st + OFF_BL + off) = vl;
    }
}

// per-warp compute of one 64-wide K chunk: acc += Ah*Bh + Ah*Bl + Al*Bh
__device__ __forceinline__ void mma_chunk(uint32_t sst, float (&acc)[4][8][4],
                                          int wm, int wn, int lane) {
    const int lr = lane & 7;     // row within 8x8 matrix
    const int lm = lane >> 3;    // which 8x8 matrix of the x4
#pragma unroll
    for (int p = 0; p < 3; p++) {
        const uint32_t aBase = sst + ((p == 2) ? OFF_AL : OFF_AH);
        const uint32_t bBase = sst + ((p == 1) ? OFF_BL : OFF_BH);
#pragma unroll
        for (int kk = 0; kk < 4; kk++) {
            uint32_t ar[16], br[16];
#pragma unroll
            for (int mi = 0; mi < 4; mi++) {
                int row = wm * 64 + mi * 16 + lr + ((lm & 1) ? 8 : 0);
                int kc  = kk * 16 + ((lm & 2) ? 8 : 0);
                ldsm4(ar + mi * 4, aBase + SWZ((uint32_t)(row * 128 + kc * 2)));
            }
#pragma unroll
            for (int bj = 0; bj < 4; bj++) {
                int n  = wn * 64 + bj * 16 + lr + ((lm & 2) ? 8 : 0);
                int kc = kk * 16 + ((lm & 1) ? 8 : 0);
                ldsm4(br + bj * 4, bBase + SWZ((uint32_t)(n * 128 + kc * 2)));
            }
#pragma unroll
            for (int mi = 0; mi < 4; mi++)
#pragma unroll
                for (int nj = 0; nj < 8; nj++) {
                    int base = (nj >> 1) * 4 + (nj & 1) * 2;
                    mma16816(acc[mi][nj], ar + mi * 4, br[base], br[base + 1]);
                }
        }
    }
}

// ---------------- 1. stable counting sort ------------------------------------
__global__ void __launch_bounds__(1024) sort_kernel(const int* __restrict__ idx)
{
    __shared__ int s[NGRP][1024];
    __shared__ int s_base[NGRP + 1];
    const int t = threadIdx.x;
    const int per = BATCH / 1024;
    const int base = t * per;

    int cnt[NGRP];
#pragma unroll
    for (int g = 0; g < NGRP; g++) cnt[g] = 0;
    for (int i = 0; i < per; i++) {
        int v = idx[base + i];
#pragma unroll
        for (int g = 0; g < NGRP; g++) cnt[g] += (v == g);
    }
#pragma unroll
    for (int g = 0; g < NGRP; g++) s[g][t] = cnt[g];
    __syncthreads();

    for (int d = 1; d < 1024; d <<= 1) {
        int v[NGRP];
        if (t >= d) {
#pragma unroll
            for (int g = 0; g < NGRP; g++) v[g] = s[g][t - d];
        }
        __syncthreads();
        if (t >= d) {
#pragma unroll
            for (int g = 0; g < NGRP; g++) s[g][t] += v[g];
        }
        __syncthreads();
    }

    if (t == 0) {
        int acc = 0;
#pragma unroll
        for (int g = 0; g < NGRP; g++) { s_base[g] = acc; acc += s[g][1023]; }
        s_base[NGRP] = acc;
        for (int g = 0; g <= NGRP; g++) g_off[g] = s_base[g];
    }
    __syncthreads();

    int pos[NGRP];
#pragma unroll
    for (int g = 0; g < NGRP; g++) pos[g] = s_base[g] + s[g][t] - cnt[g];

    for (int i = 0; i < per; i++) {
        int v = idx[base + i];
        int p = 0;
#pragma unroll
        for (int g = 0; g < NGRP; g++) if (v == g) p = pos[g]++;
        g_perm[p] = base + i;
    }
}

// ---------------- 2. weight transpose + bf16 split ---------------------------
__global__ void __launch_bounds__(256) prep_weights(const float* __restrict__ W1,
                                                    const float* __restrict__ W2)
{
    const int N1 = NGRP * DF * DIN;
    int t = blockIdx.x * 256 + threadIdx.x;
    if (t < N1) {
        int g = t / (DF * DIN);
        int r = t - g * DF * DIN;
        int n = r / DIN;
        int k = r - n * DIN;
        float x = W1[(size_t)g * DIN * DF + (size_t)k * DF + n];
        __nv_bfloat16 h = __float2bfloat16(x);
        g_W1Th[t] = h;
        g_W1Tl[t] = __float2bfloat16(x - __bfloat162float(h));
    } else if (t < N1 + DF * DF) {
        int r = t - N1;
        int n = r / DF;
        int k = r - n * DF;
        float x = W2[(size_t)k * DF + n];
        __nv_bfloat16 h = __float2bfloat16(x);
        g_W2Th[r] = h;
        g_W2Tl[r] = __float2bfloat16(x - __bfloat162float(h));
    }
}

// ---------------- 3. GEMM1: h1 = sigmoid(state[perm] @ W1[g] + b1[g]) --------
__global__ void __launch_bounds__(256) gemm1_mma(const float* __restrict__ state,
                                                 const float* __restrict__ b1)
{
    int bid = blockIdx.x;
    int g = -1, row_start = 0, row_end = 0, acct = 0;
#pragma unroll
    for (int gg = 0; gg < NGRP; gg++) {
        int c0 = g_off[gg], c1 = g_off[gg + 1];
        int nt = (c1 - c0 + 127) >> 7;
        if (g < 0 && bid < acct + nt) { g = gg; row_start = c0 + (bid - acct) * 128; row_end = c1; }
        acct += nt;
    }
    if (g < 0) return;

    extern __shared__ __align__(1024) char smem[];
    const uint32_t sbase = smem_u32(smem);
    const int tid = threadIdx.x, wid = tid >> 5, lane = tid & 31;
    const int wm = wid >> 2, wn = wid & 3;

    const __nv_bfloat16* WH = g_W1Th + (size_t)g * DF * DIN;
    const __nv_bfloat16* WL = g_W1Tl + (size_t)g * DF * DIN;

    // A gather pointers (rows fixed across chunks)
    const int seg = tid & 7;
    const int rb = tid >> 3;
    const float* asrc[4];
    bool aval[4];
#pragma unroll
    for (int i = 0; i < 4; i++) {
        int m = row_start + rb + i * 32;
        aval[i] = (m < row_end);
        asrc[i] = aval[i] ? (state + (size_t)g_perm[m] * DIN + seg * 8) : state;
    }

    float acc[4][8][4];
#pragma unroll
    for (int a = 0; a < 4; a++)
#pragma unroll
        for (int b = 0; b < 8; b++)
#pragma unroll
            for (int c = 0; c < 4; c++) acc[a][b][c] = 0.f;

    float4 pa[4][2];
    // prefetch chunk 0
#pragma unroll
    for (int i = 0; i < 4; i++) {
        pa[i][0] = aval[i] ? *(const float4*)(asrc[i])     : make_float4(0, 0, 0, 0);
        pa[i][1] = aval[i] ? *(const float4*)(asrc[i] + 4) : make_float4(0, 0, 0, 0);
    }
    // stage chunk 0
    {
        char* st = smem;
#pragma unroll
        for (int i = 0; i < 4; i++) {
            float f[8] = { pa[i][0].x, pa[i][0].y, pa[i][0].z, pa[i][0].w,
                           pa[i][1].x, pa[i][1].y, pa[i][1].z, pa[i][1].w };
            float hf[8], lf[8];
#pragma unroll
            for (int j = 0; j < 8; j++) {
                __nv_bfloat16 h = __float2bfloat16(f[j]);
                hf[j] = __bfloat162float(h);
                lf[j] = f[j] - hf[j];
            }
            uint4 uh = { pack_bf2(hf[0], hf[1]), pack_bf2(hf[2], hf[3]),
                         pack_bf2(hf[4], hf[5]), pack_bf2(hf[6], hf[7]) };
            uint4 ul = { pack_bf2(lf[0], lf[1]), pack_bf2(lf[2], lf[3]),
                         pack_bf2(lf[4], lf[5]), pack_bf2(lf[6], lf[7]) };
            uint32_t off = SWZ((uint32_t)((rb + i * 32) * 128 + seg * 16));
            *(uint4*)(st + OFF_AH + off) = uh;
            *(uint4*)(st + OFF_AL + off) = ul;
        }
        stage_b(st, WH, WL, 0, DIN, tid);
    }

    for (int c = 0; c < 8; c++) {
        __syncthreads();
        if (c < 7) {
            const int k0 = (c + 1) * 64;
#pragma unroll
            for (int i = 0; i < 4; i++) {
                pa[i][0] = aval[i] ? *(const float4*)(asrc[i] + k0)     : make_float4(0, 0, 0, 0);
                pa[i][1] = aval[i] ? *(const float4*)(asrc[i] + k0 + 4) : make_float4(0, 0, 0, 0);
            }
        }
        mma_chunk(sbase + (uint32_t)(c & 1) * STAGE_B, acc, wm, wn, lane);
        __syncthreads();
        if (c < 7) {
            char* st = smem + ((c + 1) & 1) * STAGE_B;
#pragma unroll
            for (int i = 0; i < 4; i++) {
                float f[8] = { pa[i][0].x, pa[i][0].y, pa[i][0].z, pa[i][0].w,
                               pa[i][1].x, pa[i][1].y, pa[i][1].z, pa[i][1].w };
                float hf[8], lf[8];
#pragma unroll
                for (int j = 0; j < 8; j++) {
                    __nv_bfloat16 h = __float2bfloat16(f[j]);
                    hf[j] = __bfloat162float(h);
                    lf[j] = f[j] - hf[j];
                }
                uint4 uh = { pack_bf2(hf[0], hf[1]), pack_bf2(hf[2], hf[3]),
                             pack_bf2(hf[4], hf[5]), pack_bf2(hf[6], hf[7]) };
                uint4 ul = { pack_bf2(lf[0], lf[1]), pack_bf2(lf[2], lf[3]),
                             pack_bf2(lf[4], lf[5]), pack_bf2(lf[6], lf[7]) };
                uint32_t off = SWZ((uint32_t)((rb + i * 32) * 128 + seg * 16));
                *(uint4*)(st + OFF_AH + off) = uh;
                *(uint4*)(st + OFF_AL + off) = ul;
            }
            stage_b(st, WH, WL, (c + 1) * 64, DIN, tid);
        }
    }

    // epilogue: bias + sigmoid + bf16 hi/lo split -> g_h1h/g_h1l
    const float* bb = b1 + g * DF;
#pragma unroll
    for (int mi = 0; mi < 4; mi++) {
        int r1 = row_start + wm * 64 + mi * 16 + (lane >> 2);
        int r2 = r1 + 8;
#pragma unroll
        for (int nj = 0; nj < 8; nj++) {
            int n = wn * 64 + nj * 8 + (lane & 3) * 2;
            float* a = acc[mi][nj];
            if (r1 < row_end) {
                float s0 = 1.f / (1.f + __expf(-(a[0] + bb[n])));
                float s1 = 1.f / (1.f + __expf(-(a[1] + bb[n + 1])));
                float l0 = s0 - __bfloat162float(__float2bfloat16(s0));
                float l1 = s1 - __bfloat162float(__float2bfloat16(s1));
                *(uint32_t*)(g_h1h + (size_t)r1 * DF + n) = pack_bf2(s0, s1);
                *(uint32_t*)(g_h1l + (size_t)r1 * DF + n) = pack_bf2(l0, l1);
            }
            if (r2 < row_end) {
                float s0 = 1.f / (1.f + __expf(-(a[2] + bb[n])));
                float s1 = 1.f / (1.f + __expf(-(a[3] + bb[n + 1])));
                float l0 = s0 - __bfloat162float(__float2bfloat16(s0));
                float l1 = s1 - __bfloat162float(__float2bfloat16(s1));
                *(uint32_t*)(g_h1h + (size_t)r2 * DF + n) = pack_bf2(s0, s1);
                *(uint32_t*)(g_h1l + (size_t)r2 * DF + n) = pack_bf2(l0, l1);
            }
        }
    }
}

// ---------------- 4. GEMM2 + fused Q head ------------------------------------
__global__ void __launch_bounds__(256) gemm2_mma(const float* __restrict__ b2,
                                                 const int* __restrict__ action,
                                                 const int* __restrict__ idx,
                                                 const float* __restrict__ Wq,
                                                 const float* __restrict__ bq,
                                                 float* __restrict__ out)
{
    const int m0 = blockIdx.x * 128;
    extern __shared__ __align__(1024) char smem[];
    const uint32_t sbase = smem_u32(smem);
    const int tid = threadIdx.x, wid = tid >> 5, lane = tid & 31;
    const int wm = wid >> 2, wn = wid & 3;

    const int seg = tid & 7;
    const int rb = tid >> 3;

    float acc[4][8][4];
#pragma unroll
    for (int a = 0; a < 4; a++)
#pragma unroll
        for (int b = 0; b < 8; b++)
#pragma unroll
            for (int c = 0; c < 4; c++) acc[a][b][c] = 0.f;

    uint4 ph[4], pl[4];
#pragma unroll
    for (int i = 0; i < 4; i++) {
        size_t gofs = (size_t)(m0 + rb + i * 32) * DF + seg * 8;
        ph[i] = *(const uint4*)(g_h1h + gofs);
        pl[i] = *(const uint4*)(g_h1l + gofs);
    }
    {
        char* st = smem;
#pragma unroll
        for (int i = 0; i < 4; i++) {
            uint32_t off = SWZ((uint32_t)((rb + i * 32) * 128 + seg * 16));
            *(uint4*)(st + OFF_AH + off) = ph[i];
            *(uint4*)(st + OFF_AL + off) = pl[i];
        }
        stage_b(st, g_W2Th, g_W2Tl, 0, DF, tid);
    }

    for (int c = 0; c < 4; c++) {
        __syncthreads();
        if (c < 3) {
            const int k0 = (c + 1) * 64;
#pragma unroll
            for (int i = 0; i < 4; i++) {
                size_t gofs = (size_t)(m0 + rb + i * 32) * DF + k0 + seg * 8;
                ph[i] = *(const uint4*)(g_h1h + gofs);
                pl[i] = *(const uint4*)(g_h1l + gofs);
            }
        }
        mma_chunk(sbase + (uint32_t)(c & 1) * STAGE_B, acc, wm, wn, lane);
        __syncthreads();
        if (c < 3) {
            char* st = smem + ((c + 1) & 1) * STAGE_B;
#pragma unroll
            for (int i = 0; i < 4; i++) {
                uint32_t off = SWZ((uint32_t)((rb + i * 32) * 128 + seg * 16));
                *(uint4*)(st + OFF_AH + off) = ph[i];
                *(uint4*)(st + OFF_AL + off) = pl[i];
            }
            stage_b(st, g_W2Th, g_W2Tl, (c + 1) * 64, DF, tid);
        }
    }

    // epilogue phase 1: relu(acc + b2) -> smem fp32 [128][256]
    float* s_hf = (float*)smem;
#pragma unroll
    for (int mi = 0; mi < 4; mi++) {
        int lr1 = wm * 64 + mi * 16 + (lane >> 2);
        int lr2 = lr1 + 8;
#pragma unroll
        for (int nj = 0; nj < 8; nj++) {
            int n = wn * 64 + nj * 8 + (lane & 3) * 2;
            float* a = acc[mi][nj];
            s_hf[lr1 * DF + n]     = fmaxf(a[0] + b2[n], 0.f);
            s_hf[lr1 * DF + n + 1] = fmaxf(a[1] + b2[n + 1], 0.f);
            s_hf[lr2 * DF + n]     = fmaxf(a[2] + b2[n], 0.f);
            s_hf[lr2 * DF + n + 1] = fmaxf(a[3] + b2[n + 1], 0.f);
        }
    }
    __syncthreads();

    // epilogue phase 2: per-row dot with Wq[idx,:,action] + tanh
    for (int i = 0; i < 16; i++) {
        const int lr = wid * 16 + i;
        const int m = m0 + lr;
        const int gi = idx[m];
        const int ai = action[m];
        const float* wq = Wq + (size_t)gi * DF * NOUT + ai;
        const float* row = s_hf + lr * DF;
        float sum = 0.f;
#pragma unroll
        for (int f = lane; f < DF; f += 32)
            sum += row[f] * wq[(size_t)f * NOUT];
#pragma unroll
        for (int s = 16; s; s >>= 1) sum += __shfl_xor_sync(0xFFFFFFFFu, sum, s);
        if (lane == 0) out[m] = tanhf(sum + bq[gi * NOUT + ai]);
    }
}

// ---------------- launcher ---------------------------------------------------
extern "C" void kernel_launch(void* const* d_in, const int* in_sizes, int n_in,
                              void* d_out, int out_size)
{
    const float* state  = (const float*)d_in[0];
    const int*   action = (const int*)d_in[1];
    const int*   idx    = (const int*)d_in[2];
    const float* W1     = (const float*)d_in[3];
    const float* b1     = (const float*)d_in[4];
    const float* W2     = (const float*)d_in[5];
    const float* b2     = (const float*)d_in[6];
    const float* Wq     = (const float*)d_in[7];
    const float* bq     = (const float*)d_in[8];
    float* out = (float*)d_out;

    cudaFuncSetAttribute(gemm1_mma, cudaFuncAttributeMaxDynamicSharedMemorySize, SMEM_TOTAL);
    cudaFuncSetAttribute(gemm2_mma, cudaFuncAttributeMaxDynamicSharedMemorySize, SMEM_TOTAL);

    sort_kernel<<<1, 1024>>>(idx);
    prep_weights<<<(NGRP * DF * DIN + DF * DF + 255) / 256, 256>>>(W1, W2);
    gemm1_mma<<<517, 256, SMEM_TOTAL>>>(state, b1);
    gemm2_mma<<<BATCH / 128, 256, SMEM_TOTAL>>>(b2, action, idx, Wq, bq, out);
}

// round 7
// speedup vs baseline: 2.7260x; 1.0787x over previous
#include <cuda_runtime.h>
#include <cuda_bf16.h>
#include <cstdint>

#define BATCH 65536
#define NGRP  6
#define DIN   512
#define DF    256
#define NOUT  18

// ---------------- scratch (static device globals) ----------------------------
__device__ int g_perm[BATCH];
__device__ int g_off[NGRP + 1];
__device__ __nv_bfloat16 g_sth[(size_t)BATCH * DIN];  // state split hi (orig order)
__device__ __nv_bfloat16 g_stl[(size_t)BATCH * DIN];  // state split lo
__device__ __nv_bfloat16 g_W1Th[NGRP * DF * DIN];     // [g][n][k] K-major hi
__device__ __nv_bfloat16 g_W1Tl[NGRP * DF * DIN];
__device__ __nv_bfloat16 g_W2Th[DF * DF];             // [n][k]
__device__ __nv_bfloat16 g_W2Tl[DF * DF];
__device__ __nv_bfloat16 g_h1h[(size_t)BATCH * DF];   // sorted-row order
__device__ __nv_bfloat16 g_h1l[(size_t)BATCH * DF];

// ---------------- helpers ----------------------------------------------------
__device__ __forceinline__ uint32_t smem_u32(const void* p) {
    uint32_t a;
    asm("{ .reg .u64 t; cvta.to.shared.u64 t, %1; cvt.u32.u64 %0, t; }" : "=r"(a) : "l"(p));
    return a;
}
#define SWZ(x) ((x) ^ (((x) >> 3) & 0x70))

__device__ __forceinline__ void cp16(uint32_t dst, const void* src) {
    asm volatile("cp.async.cg.shared.global [%0], [%1], 16;" :: "r"(dst), "l"(src));
}
#define CP_COMMIT() asm volatile("cp.async.commit_group;" ::: "memory")

__device__ __forceinline__ void ldsm4(uint32_t* r, uint32_t addr) {
    asm volatile("ldmatrix.sync.aligned.m8n8.x4.shared.b16 {%0,%1,%2,%3}, [%4];"
                 : "=r"(r[0]), "=r"(r[1]), "=r"(r[2]), "=r"(r[3]) : "r"(addr));
}
__device__ __forceinline__ void mma16816(float* d, const uint32_t* a, uint32_t b0, uint32_t b1) {
    asm volatile("mma.sync.aligned.m16n8k16.row.col.f32.bf16.bf16.f32 "
                 "{%0,%1,%2,%3}, {%4,%5,%6,%7}, {%8,%9}, {%0,%1,%2,%3};"
                 : "+f"(d[0]), "+f"(d[1]), "+f"(d[2]), "+f"(d[3])
                 : "r"(a[0]), "r"(a[1]), "r"(a[2]), "r"(a[3]), "r"(b0), "r"(b1));
}
__device__ __forceinline__ uint32_t pack_bf2(float a, float b) {
    __nv_bfloat162 t = __floats2bfloat162_rn(a, b);
    return *reinterpret_cast<uint32_t*>(&t);
}

// smem stage layout (bytes, relative to stage base)
#define OFF_AH 0        // 128 rows x 128B
#define OFF_AL 16384
#define OFF_BH 32768    // 256 rows x 128B
#define OFF_BL 65536
#define STAGE_B 98304
#define SMEM_TOTAL (2 * STAGE_B)

// per-warp compute of one 64-wide K chunk, warp tile 32x64:
// acc += Ah*Bh + Ah*Bl + Al*Bh
__device__ __forceinline__ void mma_chunk32(uint32_t sst, float (&acc)[2][8][4],
                                            int wm, int wn, int lane) {
    const int lr = lane & 7;
    const int lm = lane >> 3;
#pragma unroll
    for (int p = 0; p < 3; p++) {
        const uint32_t aBase = sst + ((p == 2) ? OFF_AL : OFF_AH);
        const uint32_t bBase = sst + ((p == 1) ? OFF_BL : OFF_BH);
#pragma unroll
        for (int kk = 0; kk < 4; kk++) {
            uint32_t ar[8], br[16];
#pragma unroll
            for (int mi = 0; mi < 2; mi++) {
                int row = wm * 32 + mi * 16 + lr + ((lm & 1) ? 8 : 0);
                int kc  = kk * 16 + ((lm & 2) ? 8 : 0);
                ldsm4(ar + mi * 4, aBase + SWZ((uint32_t)(row * 128 + kc * 2)));
            }
#pragma unroll
            for (int bj = 0; bj < 4; bj++) {
                int n  = wn * 64 + bj * 16 + lr + ((lm & 2) ? 8 : 0);
                int kc = kk * 16 + ((lm & 1) ? 8 : 0);
                ldsm4(br + bj * 4, bBase + SWZ((uint32_t)(n * 128 + kc * 2)));
            }
#pragma unroll
            for (int mi = 0; mi < 2; mi++)
#pragma unroll
                for (int nj = 0; nj < 8; nj++) {
                    int base = (nj >> 1) * 4 + (nj & 1) * 2;
                    mma16816(acc[mi][nj], ar + mi * 4, br[base], br[base + 1]);
                }
        }
    }
}

// ---------------- 1. stable counting sort ------------------------------------
__global__ void __launch_bounds__(1024) sort_kernel(const int* __restrict__ idx)
{
    __shared__ int s[NGRP][1024];
    __shared__ int s_base[NGRP + 1];
    const int t = threadIdx.x;
    const int per = BATCH / 1024;
    const int base = t * per;

    int cnt[NGRP];
#pragma unroll
    for (int g = 0; g < NGRP; g++) cnt[g] = 0;
    for (int i = 0; i < per; i++) {
        int v = idx[base + i];
#pragma unroll
        for (int g = 0; g < NGRP; g++) cnt[g] += (v == g);
    }
#pragma unroll
    for (int g = 0; g < NGRP; g++) s[g][t] = cnt[g];
    __syncthreads();

    for (int d = 1; d < 1024; d <<= 1) {
        int v[NGRP];
        if (t >= d) {
#pragma unroll
            for (int g = 0; g < NGRP; g++) v[g] = s[g][t - d];
        }
        __syncthreads();
        if (t >= d) {
#pragma unroll
            for (int g = 0; g < NGRP; g++) s[g][t] += v[g];
        }
        __syncthreads();
    }

    if (t == 0) {
        int acc = 0;
#pragma unroll
        for (int g = 0; g < NGRP; g++) { s_base[g] = acc; acc += s[g][1023]; }
        s_base[NGRP] = acc;
        for (int g = 0; g <= NGRP; g++) g_off[g] = s_base[g];
    }
    __syncthreads();

    int pos[NGRP];
#pragma unroll
    for (int g = 0; g < NGRP; g++) pos[g] = s_base[g] + s[g][t] - cnt[g];

    for (int i = 0; i < per; i++) {
        int v = idx[base + i];
        int p = 0;
#pragma unroll
        for (int g = 0; g < NGRP; g++) if (v == g) p = pos[g]++;
        g_perm[p] = base + i;
    }
}

// ---------------- 2a. state split fp32 -> bf16 hi/lo (orig order) ------------
__global__ void __launch_bounds__(256) prep_state(const float* __restrict__ state)
{
    size_t p = (size_t)blockIdx.x * 256 + threadIdx.x;   // float4 index
    float4 v = ((const float4*)state)[p];
    float f[4] = { v.x, v.y, v.z, v.w };
    float hf[4], lf[4];
#pragma unroll
    for (int j = 0; j < 4; j++) {
        __nv_bfloat16 h = __float2bfloat16(f[j]);
        hf[j] = __bfloat162float(h);
        lf[j] = f[j] - hf[j];
    }
    uint2 uh = { pack_bf2(hf[0], hf[1]), pack_bf2(hf[2], hf[3]) };
    uint2 ul = { pack_bf2(lf[0], lf[1]), pack_bf2(lf[2], lf[3]) };
    ((uint2*)g_sth)[p] = uh;
    ((uint2*)g_stl)[p] = ul;
}

// ---------------- 2b. weight transpose + bf16 split --------------------------
__global__ void __launch_bounds__(256) prep_weights(const float* __restrict__ W1,
                                                    const float* __restrict__ W2)
{
    const int N1 = NGRP * DF * DIN;
    int t = blockIdx.x * 256 + threadIdx.x;
    if (t < N1) {
        int g = t / (DF * DIN);
        int r = t - g * DF * DIN;
        int n = r / DIN;
        int k = r - n * DIN;
        float x = W1[(size_t)g * DIN * DF + (size_t)k * DF + n];
        __nv_bfloat16 h = __float2bfloat16(x);
        g_W1Th[t] = h;
        g_W1Tl[t] = __float2bfloat16(x - __bfloat162float(h));
    } else if (t < N1 + DF * DF) {
        int r = t - N1;
        int n = r / DF;
        int k = r - n * DF;
        float x = W2[(size_t)k * DF + n];
        __nv_bfloat16 h = __float2bfloat16(x);
        g_W2Th[r] = h;
        g_W2Tl[r] = __float2bfloat16(x - __bfloat162float(h));
    }
}

// ---------------- 3. GEMM1: h1 = sigmoid(state[perm] @ W1[g] + b1[g]) --------
// tile 128(M) x 256(N), K-chunk 64, 512 threads, cp.async double buffer
__global__ void __launch_bounds__(512) gemm1_mma(const float* __restrict__ b1)
{
    int bid = blockIdx.x;
    int g = -1, row_start = 0, row_end = 0, acct = 0;
#pragma unroll
    for (int gg = 0; gg < NGRP; gg++) {
        int c0 = g_off[gg], c1 = g_off[gg + 1];
        int nt = (c1 - c0 + 127) >> 7;
        if (g < 0 && bid < acct + nt) { g = gg; row_start = c0 + (bid - acct) * 128; row_end = c1; }
        acct += nt;
    }
    if (g < 0) return;

    extern __shared__ __align__(1024) char smem[];
    __shared__ int s_row[128];
    const uint32_t sbase = smem_u32(smem);
    const int tid = threadIdx.x, wid = tid >> 5, lane = tid & 31;
    const int wm = wid >> 2, wn = wid & 3;

    if (tid < 128) {
        int r = row_start + tid;
        s_row[tid] = g_perm[min(r, BATCH - 1)];
    }
    __syncthreads();

    const __nv_bfloat16* WH = g_W1Th + (size_t)g * DF * DIN;
    const __nv_bfloat16* WL = g_W1Tl + (size_t)g * DF * DIN;
    const int seg = tid & 7, rt0 = tid >> 3;   // rt0 in 0..63

    float acc[2][8][4];
#pragma unroll
    for (int a = 0; a < 2; a++)
#pragma unroll
        for (int b = 0; b < 8; b++)
#pragma unroll
            for (int c = 0; c < 4; c++) acc[a][b][c] = 0.f;

    // stage-issue lambda
    auto issue = [&](int c) {
        uint32_t sst = sbase + (uint32_t)(c & 1) * STAGE_B;
        const int k0 = c * 64;
#pragma unroll
        for (int it = 0; it < 2; it++) {
            int rt = rt0 + it * 64;
            size_t rb = (size_t)s_row[rt] * DIN + k0 + seg * 8;
            uint32_t off = SWZ((uint32_t)(rt * 128 + seg * 16));
            cp16(sst + OFF_AH + off, g_sth + rb);
            cp16(sst + OFF_AL + off, g_stl + rb);
        }
#pragma unroll
        for (int it = 0; it < 4; it++) {
            int rn = rt0 + it * 64;
            size_t rb = (size_t)rn * DIN + k0 + seg * 8;
            uint32_t off = SWZ((uint32_t)(rn * 128 + seg * 16));
            cp16(sst + OFF_BH + off, WH + rb);
            cp16(sst + OFF_BL + off, WL + rb);
        }
        CP_COMMIT();
    };

    issue(0);
    for (int c = 0; c < 8; c++) {
        if (c < 7) {
            issue(c + 1);
            asm volatile("cp.async.wait_group 1;" ::: "memory");
        } else {
            asm volatile("cp.async.wait_group 0;" ::: "memory");
        }
        __syncthreads();
        mma_chunk32(sbase + (uint32_t)(c & 1) * STAGE_B, acc, wm, wn, lane);
        __syncthreads();
    }

    // epilogue: bias + sigmoid + bf16 hi/lo split -> g_h1h/g_h1l
    const float* bb = b1 + g * DF;
#pragma unroll
    for (int mi = 0; mi < 2; mi++) {
        int r1 = row_start + wm * 32 + mi * 16 + (lane >> 2);
        int r2 = r1 + 8;
#pragma unroll
        for (int nj = 0; nj < 8; nj++) {
            int n = wn * 64 + nj * 8 + (lane & 3) * 2;
            float* a = acc[mi][nj];
            if (r1 < row_end) {
                float s0 = 1.f / (1.f + __expf(-(a[0] + bb[n])));
                float s1 = 1.f / (1.f + __expf(-(a[1] + bb[n + 1])));
                float l0 = s0 - __bfloat162float(__float2bfloat16(s0));
                float l1 = s1 - __bfloat162float(__float2bfloat16(s1));
                *(uint32_t*)(g_h1h + (size_t)r1 * DF + n) = pack_bf2(s0, s1);
                *(uint32_t*)(g_h1l + (size_t)r1 * DF + n) = pack_bf2(l0, l1);
            }
            if (r2 < row_end) {
                float s0 = 1.f / (1.f + __expf(-(a[2] + bb[n])));
                float s1 = 1.f / (1.f + __expf(-(a[3] + bb[n + 1])));
                float l0 = s0 - __bfloat162float(__float2bfloat16(s0));
                float l1 = s1 - __bfloat162float(__float2bfloat16(s1));
                *(uint32_t*)(g_h1h + (size_t)r2 * DF + n) = pack_bf2(s0, s1);
                *(uint32_t*)(g_h1l + (size_t)r2 * DF + n) = pack_bf2(l0, l1);
            }
        }
    }
}

// ---------------- 4. GEMM2 + fused Q head ------------------------------------
__global__ void __launch_bounds__(512) gemm2_mma(const float* __restrict__ b2,
                                                 const int* __restrict__ action,
                                                 const int* __restrict__ idx,
                                                 const float* __restrict__ Wq,
                                                 const float* __restrict__ bq,
                                                 float* __restrict__ out)
{
    const int m0 = blockIdx.x * 128;
    extern __shared__ __align__(1024) char smem[];
    const uint32_t sbase = smem_u32(smem);
    const int tid = threadIdx.x, wid = tid >> 5, lane = tid & 31;
    const int wm = wid >> 2, wn = wid & 3;
    const int seg = tid & 7, rt0 = tid >> 3;

    float acc[2][8][4];
#pragma unroll
    for (int a = 0; a < 2; a++)
#pragma unroll
        for (int b = 0; b < 8; b++)
#pragma unroll
            for (int c = 0; c < 4; c++) acc[a][b][c] = 0.f;

    auto issue = [&](int c) {
        uint32_t sst = sbase + (uint32_t)(c & 1) * STAGE_B;
        const int k0 = c * 64;
#pragma unroll
        for (int it = 0; it < 2; it++) {
            int rt = rt0 + it * 64;
            size_t rb = (size_t)(m0 + rt) * DF + k0 + seg * 8;
            uint32_t off = SWZ((uint32_t)(rt * 128 + seg * 16));
            cp16(sst + OFF_AH + off, g_h1h + rb);
            cp16(sst + OFF_AL + off, g_h1l + rb);
        }
#pragma unroll
        for (int it = 0; it < 4; it++) {
            int rn = rt0 + it * 64;
            size_t rb = (size_t)rn * DF + k0 + seg * 8;
            uint32_t off = SWZ((uint32_t)(rn * 128 + seg * 16));
            cp16(sst + OFF_BH + off, g_W2Th + rb);
            cp16(sst + OFF_BL + off, g_W2Tl + rb);
        }
        CP_COMMIT();
    };

    issue(0);
    for (int c = 0; c < 4; c++) {
        if (c < 3) {
            issue(c + 1);
            asm volatile("cp.async.wait_group 1;" ::: "memory");
        } else {
            asm volatile("cp.async.wait_group 0;" ::: "memory");
        }
        __syncthreads();
        mma_chunk32(sbase + (uint32_t)(c & 1) * STAGE_B, acc, wm, wn, lane);
        __syncthreads();
    }

    // epilogue phase 1: relu(acc + b2) -> smem fp32 [128][256]
    float* s_hf = (float*)smem;
#pragma unroll
    for (int mi = 0; mi < 2; mi++) {
        int lr1 = wm * 32 + mi * 16 + (lane >> 2);
        int lr2 = lr1 + 8;
#pragma unroll
        for (int nj = 0; nj < 8; nj++) {
            int n = wn * 64 + nj * 8 + (lane & 3) * 2;
            float* a = acc[mi][nj];
            s_hf[lr1 * DF + n]     = fmaxf(a[0] + b2[n], 0.f);
            s_hf[lr1 * DF + n + 1] = fmaxf(a[1] + b2[n + 1], 0.f);
            s_hf[lr2 * DF + n]     = fmaxf(a[2] + b2[n], 0.f);
            s_hf[lr2 * DF + n + 1] = fmaxf(a[3] + b2[n + 1], 0.f);
        }
    }
    __syncthreads();

    // epilogue phase 2: per-row dot with Wq[idx,:,action] + tanh
#pragma unroll
    for (int i = 0; i < 8; i++) {
        const int lr = wid * 8 + i;
        const int m = m0 + lr;
        const int gi = idx[m];
        const int ai = action[m];
        const float* wq = Wq + (size_t)gi * DF * NOUT + ai;
        const float* row = s_hf + lr * DF;
        float sum = 0.f;
#pragma unroll
        for (int f = lane; f < DF; f += 32)
            sum += row[f] * wq[(size_t)f * NOUT];
#pragma unroll
        for (int s = 16; s; s >>= 1) sum += __shfl_xor_sync(0xFFFFFFFFu, sum, s);
        if (lane == 0) out[m] = tanhf(sum + bq[gi * NOUT + ai]);
    }
}

// ---------------- launcher ---------------------------------------------------
extern "C" void kernel_launch(void* const* d_in, const int* in_sizes, int n_in,
                              void* d_out, int out_size)
{
    const float* state  = (const float*)d_in[0];
    const int*   action = (const int*)d_in[1];
    const int*   idx    = (const int*)d_in[2];
    const float* W1     = (const float*)d_in[3];
    const float* b1     = (const float*)d_in[4];
    const float* W2     = (const float*)d_in[5];
    const float* b2     = (const float*)d_in[6];
    const float* Wq     = (const float*)d_in[7];
    const float* bq     = (const float*)d_in[8];
    float* out = (float*)d_out;

    cudaFuncSetAttribute(gemm1_mma, cudaFuncAttributeMaxDynamicSharedMemorySize, SMEM_TOTAL);
    cudaFuncSetAttribute(gemm2_mma, cudaFuncAttributeMaxDynamicSharedMemorySize, SMEM_TOTAL);

    sort_kernel<<<1, 1024>>>(idx);
    prep_state<<<(BATCH * DIN / 4) / 256, 256>>>(state);
    prep_weights<<<(NGRP * DF * DIN + DF * DF + 255) / 256, 256>>>(W1, W2);
    gemm1_mma<<<518, 512, SMEM_TOTAL>>>(b1);
    gemm2_mma<<<BATCH / 128, 512, SMEM_TOTAL>>>(b2, action, idx, Wq, bq, out);
}

// round 8
// speedup vs baseline: 3.5244x; 1.2929x over previous
#include <cuda_runtime.h>
#include <cuda_bf16.h>
#include <cstdint>

#define BATCH 65536
#define NGRP  6
#define DIN   512
#define DF    256
#define NOUT  18

// ---------------- scratch (static device globals) ----------------------------
__device__ int g_perm[BATCH];
__device__ int g_off[NGRP + 1];
__device__ __nv_bfloat16 g_sth[(size_t)BATCH * DIN];  // state split hi (orig order)
__device__ __nv_bfloat16 g_stl[(size_t)BATCH * DIN];  // state split lo
__device__ __nv_bfloat16 g_W1Th[NGRP * DF * DIN];     // [g][n][k] K-major hi
__device__ __nv_bfloat16 g_W1Tl[NGRP * DF * DIN];
__device__ __nv_bfloat16 g_W2Th[DF * DF];             // [n][k]
__device__ __nv_bfloat16 g_W2Tl[DF * DF];
__device__ __nv_bfloat16 g_h1h[(size_t)BATCH * DF];   // sorted-row order
__device__ __nv_bfloat16 g_h1l[(size_t)BATCH * DF];
__device__ float g_qpart[(size_t)BATCH * 4];          // partial Q dots

// ---------------- helpers ----------------------------------------------------
__device__ __forceinline__ uint32_t smem_u32(const void* p) {
    uint32_t a;
    asm("{ .reg .u64 t; cvta.to.shared.u64 t, %1; cvt.u32.u64 %0, t; }" : "=r"(a) : "l"(p));
    return a;
}
#define SWZ64(x) ((x) ^ (((x) >> 3) & 0x30))

__device__ __forceinline__ void cp16(uint32_t dst, const void* src) {
    asm volatile("cp.async.cg.shared.global [%0], [%1], 16;" :: "r"(dst), "l"(src));
}
#define CP_COMMIT() asm volatile("cp.async.commit_group;" ::: "memory")

__device__ __forceinline__ void ldsm4(uint32_t* r, uint32_t addr) {
    asm volatile("ldmatrix.sync.aligned.m8n8.x4.shared.b16 {%0,%1,%2,%3}, [%4];"
                 : "=r"(r[0]), "=r"(r[1]), "=r"(r[2]), "=r"(r[3]) : "r"(addr));
}
__device__ __forceinline__ void mma16816(float* d, const uint32_t* a, uint32_t b0, uint32_t b1) {
    asm volatile("mma.sync.aligned.m16n8k16.row.col.f32.bf16.bf16.f32 "
                 "{%0,%1,%2,%3}, {%4,%5,%6,%7}, {%8,%9}, {%0,%1,%2,%3};"
                 : "+f"(d[0]), "+f"(d[1]), "+f"(d[2]), "+f"(d[3])
                 : "r"(a[0]), "r"(a[1]), "r"(a[2]), "r"(a[3]), "r"(b0), "r"(b1));
}
__device__ __forceinline__ uint32_t pack_bf2(float a, float b) {
    __nv_bfloat162 t = __floats2bfloat162_rn(a, b);
    return *reinterpret_cast<uint32_t*>(&t);
}

// smem stage layout (bytes): A/B tiles are 128 rows x 32 k x bf16 = 8KB each
#define OFF_AH 0
#define OFF_AL 8192
#define OFF_BH 16384
#define OFF_BL 24576
#define STAGE_B 32768
#define NSTAGE 3
#define SMEM_TOTAL (NSTAGE * STAGE_B)

// per-warp compute of one 32-wide K chunk, warp tile 32(M) x 64(N):
// acc += Ah*Bh + Ah*Bl + Al*Bh
__device__ __forceinline__ void mma_chunk(uint32_t sst, float (&acc)[2][8][4],
                                          int wm, int wn, int lane) {
    const int lr = lane & 7;
    const int lm = lane >> 3;
#pragma unroll
    for (int p = 0; p < 3; p++) {
        const uint32_t aBase = sst + ((p == 2) ? OFF_AL : OFF_AH);
        const uint32_t bBase = sst + ((p == 1) ? OFF_BL : OFF_BH);
#pragma unroll
        for (int kk = 0; kk < 2; kk++) {
            uint32_t ar[8], br[16];
#pragma unroll
            for (int mi = 0; mi < 2; mi++) {
                int row = wm * 32 + mi * 16 + lr + ((lm & 1) ? 8 : 0);
                int kc  = kk * 16 + ((lm & 2) ? 8 : 0);
                ldsm4(ar + mi * 4, aBase + SWZ64((uint32_t)(row * 64 + kc * 2)));
            }
#pragma unroll
            for (int bj = 0; bj < 4; bj++) {
                int n  = wn * 64 + bj * 16 + lr + ((lm & 2) ? 8 : 0);
                int kc = kk * 16 + ((lm & 1) ? 8 : 0);
                ldsm4(br + bj * 4, bBase + SWZ64((uint32_t)(n * 64 + kc * 2)));
            }
#pragma unroll
            for (int mi = 0; mi < 2; mi++)
#pragma unroll
                for (int nj = 0; nj < 8; nj++) {
                    int base = (nj >> 1) * 4 + (nj & 1) * 2;
                    mma16816(acc[mi][nj], ar + mi * 4, br[base], br[base + 1]);
                }
        }
    }
}

// ---------------- 1. stable counting sort ------------------------------------
__global__ void __launch_bounds__(1024) sort_kernel(const int* __restrict__ idx)
{
    __shared__ int s[NGRP][1024];
    __shared__ int s_base[NGRP + 1];
    const int t = threadIdx.x;
    const int per = BATCH / 1024;
    const int base = t * per;

    int cnt[NGRP];
#pragma unroll
    for (int g = 0; g < NGRP; g++) cnt[g] = 0;
    for (int i = 0; i < per; i++) {
        int v = idx[base + i];
#pragma unroll
        for (int g = 0; g < NGRP; g++) cnt[g] += (v == g);
    }
#pragma unroll
    for (int g = 0; g < NGRP; g++) s[g][t] = cnt[g];
    __syncthreads();

    for (int d = 1; d < 1024; d <<= 1) {
        int v[NGRP];
        if (t >= d) {
#pragma unroll
            for (int g = 0; g < NGRP; g++) v[g] = s[g][t - d];
        }
        __syncthreads();
        if (t >= d) {
#pragma unroll
            for (int g = 0; g < NGRP; g++) s[g][t] += v[g];
        }
        __syncthreads();
    }

    if (t == 0) {
        int acc = 0;
#pragma unroll
        for (int g = 0; g < NGRP; g++) { s_base[g] = acc; acc += s[g][1023]; }
        s_base[NGRP] = acc;
        for (int g = 0; g <= NGRP; g++) g_off[g] = s_base[g];
    }
    __syncthreads();

    int pos[NGRP];
#pragma unroll
    for (int g = 0; g < NGRP; g++) pos[g] = s_base[g] + s[g][t] - cnt[g];

    for (int i = 0; i < per; i++) {
        int v = idx[base + i];
        int p = 0;
#pragma unroll
        for (int g = 0; g < NGRP; g++) if (v == g) p = pos[g]++;
        g_perm[p] = base + i;
    }
}

// ---------------- 2a. state split fp32 -> bf16 hi/lo (orig order) ------------
__global__ void __launch_bounds__(256) prep_state(const float* __restrict__ state)
{
    size_t p = (size_t)blockIdx.x * 256 + threadIdx.x;   // float4 index
    float4 v = ((const float4*)state)[p];
    float f[4] = { v.x, v.y, v.z, v.w };
    float hf[4], lf[4];
#pragma unroll
    for (int j = 0; j < 4; j++) {
        __nv_bfloat16 h = __float2bfloat16(f[j]);
        hf[j] = __bfloat162float(h);
        lf[j] = f[j] - hf[j];
    }
    uint2 uh = { pack_bf2(hf[0], hf[1]), pack_bf2(hf[2], hf[3]) };
    uint2 ul = { pack_bf2(lf[0], lf[1]), pack_bf2(lf[2], lf[3]) };
    ((uint2*)g_sth)[p] = uh;
    ((uint2*)g_stl)[p] = ul;
}

// ---------------- 2b. weight transpose + bf16 split --------------------------
__global__ void __launch_bounds__(256) prep_weights(const float* __restrict__ W1,
                                                    const float* __restrict__ W2)
{
    const int N1 = NGRP * DF * DIN;
    int t = blockIdx.x * 256 + threadIdx.x;
    if (t < N1) {
        int g = t / (DF * DIN);
        int r = t - g * DF * DIN;
        int n = r / DIN;
        int k = r - n * DIN;
        float x = W1[(size_t)g * DIN * DF + (size_t)k * DF + n];
        __nv_bfloat16 h = __float2bfloat16(x);
        g_W1Th[t] = h;
        g_W1Tl[t] = __float2bfloat16(x - __bfloat162float(h));
    } else if (t < N1 + DF * DF) {
        int r = t - N1;
        int n = r / DF;
        int k = r - n * DF;
        float x = W2[(size_t)k * DF + n];
        __nv_bfloat16 h = __float2bfloat16(x);
        g_W2Th[r] = h;
        g_W2Tl[r] = __float2bfloat16(x - __bfloat162float(h));
    }
}

// ---------------- 3. GEMM1: h1 = sigmoid(state[perm] @ W1[g] + b1[g]) --------
// tile 128(M) x 128(N), K-chunk 32, 256 threads, 3-stage cp.async, 2 CTAs/SM
__global__ void __launch_bounds__(256, 2) gemm1_mma(const float* __restrict__ b1)
{
    int bid = blockIdx.x;
    int g = -1, row_start = 0, row_end = 0, acct = 0;
#pragma unroll
    for (int gg = 0; gg < NGRP; gg++) {
        int c0 = g_off[gg], c1 = g_off[gg + 1];
        int nt = (c1 - c0 + 127) >> 7;
        if (g < 0 && bid < acct + nt) { g = gg; row_start = c0 + (bid - acct) * 128; row_end = c1; }
        acct += nt;
    }
    if (g < 0) return;
    const int n0 = blockIdx.y * 128;

    extern __shared__ __align__(1024) char smem[];
    __shared__ int s_row[128];
    const uint32_t sbase = smem_u32(smem);
    const int tid = threadIdx.x, wid = tid >> 5, lane = tid & 31;
    const int wm = wid >> 1, wn = wid & 1;

    if (tid < 128) s_row[tid] = g_perm[min(row_start + tid, BATCH - 1)];
    __syncthreads();

    const __nv_bfloat16* WH = g_W1Th + (size_t)(g * DF + n0) * DIN;
    const __nv_bfloat16* WL = g_W1Tl + (size_t)(g * DF + n0) * DIN;
    const int seg = tid & 3, rt0 = tid >> 2;   // rt0 in 0..63

    float acc[2][8][4];
#pragma unroll
    for (int a = 0; a < 2; a++)
#pragma unroll
        for (int b = 0; b < 8; b++)
#pragma unroll
            for (int c = 0; c < 4; c++) acc[a][b][c] = 0.f;

    auto issue = [&](int c) {
        uint32_t sst = sbase + (uint32_t)(c % NSTAGE) * STAGE_B;
        const int k0 = c * 32;
#pragma unroll
        for (int it = 0; it < 2; it++) {
            int rt = rt0 + it * 64;
            size_t rb = (size_t)s_row[rt] * DIN + k0 + seg * 8;
            uint32_t off = SWZ64((uint32_t)(rt * 64 + seg * 16));
            cp16(sst + OFF_AH + off, g_sth + rb);
            cp16(sst + OFF_AL + off, g_stl + rb);
        }
#pragma unroll
        for (int it = 0; it < 2; it++) {
            int rn = rt0 + it * 64;
            size_t rb = (size_t)rn * DIN + k0 + seg * 8;
            uint32_t off = SWZ64((uint32_t)(rn * 64 + seg * 16));
            cp16(sst + OFF_BH + off, WH + rb);
            cp16(sst + OFF_BL + off, WL + rb);
        }
        CP_COMMIT();
    };

    const int CH = DIN / 32;   // 16
    issue(0); issue(1);
    for (int c = 0; c < CH; c++) {
        if (c + 2 < CH) {
            issue(c + 2);
            asm volatile("cp.async.wait_group 2;" ::: "memory");
        } else if (c + 1 < CH) {
            asm volatile("cp.async.wait_group 1;" ::: "memory");
        } else {
            asm volatile("cp.async.wait_group 0;" ::: "memory");
        }
        __syncthreads();
        mma_chunk(sbase + (uint32_t)(c % NSTAGE) * STAGE_B, acc, wm, wn, lane);
        __syncthreads();
    }

    // epilogue: bias + sigmoid + bf16 hi/lo split -> g_h1h/g_h1l
    const float* bb = b1 + g * DF + n0;
#pragma unroll
    for (int mi = 0; mi < 2; mi++) {
        int r1 = row_start + wm * 32 + mi * 16 + (lane >> 2);
        int r2 = r1 + 8;
#pragma unroll
        for (int nj = 0; nj < 8; nj++) {
            int n = wn * 64 + nj * 8 + (lane & 3) * 2;
            float* a = acc[mi][nj];
            if (r1 < row_end) {
                float s0 = 1.f / (1.f + __expf(-(a[0] + bb[n])));
                float s1 = 1.f / (1.f + __expf(-(a[1] + bb[n + 1])));
                float l0 = s0 - __bfloat162float(__float2bfloat16(s0));
                float l1 = s1 - __bfloat162float(__float2bfloat16(s1));
                *(uint32_t*)(g_h1h + (size_t)r1 * DF + n0 + n) = pack_bf2(s0, s1);
                *(uint32_t*)(g_h1l + (size_t)r1 * DF + n0 + n) = pack_bf2(l0, l1);
            }
            if (r2 < row_end) {
                float s0 = 1.f / (1.f + __expf(-(a[2] + bb[n])));
                float s1 = 1.f / (1.f + __expf(-(a[3] + bb[n + 1])));
                float l0 = s0 - __bfloat162float(__float2bfloat16(s0));
                float l1 = s1 - __bfloat162float(__float2bfloat16(s1));
                *(uint32_t*)(g_h1h + (size_t)r2 * DF + n0 + n) = pack_bf2(s0, s1);
                *(uint32_t*)(g_h1l + (size_t)r2 * DF + n0 + n) = pack_bf2(l0, l1);
            }
        }
    }
}

// ---------------- 4. GEMM2 + fused partial Q head ----------------------------
__global__ void __launch_bounds__(256, 2) gemm2_mma(const float* __restrict__ b2,
                                                    const int* __restrict__ action,
                                                    const int* __restrict__ idx,
                                                    const float* __restrict__ Wq)
{
    const int m0 = blockIdx.x * 128;
    const int n0 = blockIdx.y * 128;
    extern __shared__ __align__(1024) char smem[];
    const uint32_t sbase = smem_u32(smem);
    const int tid = threadIdx.x, wid = tid >> 5, lane = tid & 31;
    const int wm = wid >> 1, wn = wid & 1;
    const int seg = tid & 3, rt0 = tid >> 2;

    const __nv_bfloat16* WH = g_W2Th + (size_t)n0 * DF;
    const __nv_bfloat16* WL = g_W2Tl + (size_t)n0 * DF;

    float acc[2][8][4];
#pragma unroll
    for (int a = 0; a < 2; a++)
#pragma unroll
        for (int b = 0; b < 8; b++)
#pragma unroll
            for (int c = 0; c < 4; c++) acc[a][b][c] = 0.f;

    auto issue = [&](int c) {
        uint32_t sst = sbase + (uint32_t)(c % NSTAGE) * STAGE_B;
        const int k0 = c * 32;
#pragma unroll
        for (int it = 0; it < 2; it++) {
            int rt = rt0 + it * 64;
            size_t rb = (size_t)(m0 + rt) * DF + k0 + seg * 8;
            uint32_t off = SWZ64((uint32_t)(rt * 64 + seg * 16));
            cp16(sst + OFF_AH + off, g_h1h + rb);
            cp16(sst + OFF_AL + off, g_h1l + rb);
        }
#pragma unroll
        for (int it = 0; it < 2; it++) {
            int rn = rt0 + it * 64;
            size_t rb = (size_t)rn * DF + k0 + seg * 8;
            uint32_t off = SWZ64((uint32_t)(rn * 64 + seg * 16));
            cp16(sst + OFF_BH + off, WH + rb);
            cp16(sst + OFF_BL + off, WL + rb);
        }
        CP_COMMIT();
    };

    const int CH = DF / 32;    // 8
    issue(0); issue(1);
    for (int c = 0; c < CH; c++) {
        if (c + 2 < CH) {
            issue(c + 2);
            asm volatile("cp.async.wait_group 2;" ::: "memory");
        } else if (c + 1 < CH) {
            asm volatile("cp.async.wait_group 1;" ::: "memory");
        } else {
            asm volatile("cp.async.wait_group 0;" ::: "memory");
        }
        __syncthreads();
        mma_chunk(sbase + (uint32_t)(c % NSTAGE) * STAGE_B, acc, wm, wn, lane);
        __syncthreads();
    }

    // fused epilogue: partial dot of relu(acc + b2) with Wq[idx,:,action]
    const int slot = blockIdx.y * 2 + wn;      // 0..3
#pragma unroll
    for (int mi = 0; mi < 2; mi++) {
        const int rA = m0 + wm * 32 + mi * 16 + (lane >> 2);
        const int rB = rA + 8;
        const float* wqA = Wq + (size_t)idx[rA] * DF * NOUT + action[rA];
        const float* wqB = Wq + (size_t)idx[rB] * DF * NOUT + action[rB];
        float pA = 0.f, pB = 0.f;
#pragma unroll
        for (int nj = 0; nj < 8; nj++) {
            int n = n0 + wn * 64 + nj * 8 + (lane & 3) * 2;
            float* a = acc[mi][nj];
            float b20 = b2[n], b21 = b2[n + 1];
            pA += fmaxf(a[0] + b20, 0.f) * wqA[(size_t)n * NOUT]
                + fmaxf(a[1] + b21, 0.f) * wqA[(size_t)(n + 1) * NOUT];
            pB += fmaxf(a[2] + b20, 0.f) * wqB[(size_t)n * NOUT]
                + fmaxf(a[3] + b21, 0.f) * wqB[(size_t)(n + 1) * NOUT];
        }
        // reduce over the 4 lanes sharing the same rows (lane&3 varies)
        pA += __shfl_xor_sync(0xFFFFFFFFu, pA, 1);
        pA += __shfl_xor_sync(0xFFFFFFFFu, pA, 2);
        pB += __shfl_xor_sync(0xFFFFFFFFu, pB, 1);
        pB += __shfl_xor_sync(0xFFFFFFFFu, pB, 2);
        if ((lane & 3) == 0) {
            g_qpart[(size_t)rA * 4 + slot] = pA;
            g_qpart[(size_t)rB * 4 + slot] = pB;
        }
    }
}

// ---------------- 5. finish: sum partials + bias + tanh ----------------------
__global__ void __launch_bounds__(256) finishq(const int* __restrict__ action,
                                               const int* __restrict__ idx,
                                               const float* __restrict__ bq,
                                               float* __restrict__ out)
{
    const int m = blockIdx.x * 256 + threadIdx.x;
    float4 p = ((const float4*)g_qpart)[m];
    const int gi = idx[m];
    const int ai = action[m];
    out[m] = tanhf(p.x + p.y + p.z + p.w + bq[gi * NOUT + ai]);
}

// ---------------- launcher ---------------------------------------------------
extern "C" void kernel_launch(void* const* d_in, const int* in_sizes, int n_in,
                              void* d_out, int out_size)
{
    const float* state  = (const float*)d_in[0];
    const int*   action = (const int*)d_in[1];
    const int*   idx    = (const int*)d_in[2];
    const float* W1     = (const float*)d_in[3];
    const float* b1     = (const float*)d_in[4];
    const float* W2     = (const float*)d_in[5];
    const float* b2     = (const float*)d_in[6];
    const float* Wq     = (const float*)d_in[7];
    const float* bq     = (const float*)d_in[8];
    float* out = (float*)d_out;

    cudaFuncSetAttribute(gemm1_mma, cudaFuncAttributeMaxDynamicSharedMemorySize, SMEM_TOTAL);
    cudaFuncSetAttribute(gemm2_mma, cudaFuncAttributeMaxDynamicSharedMemorySize, SMEM_TOTAL);

    sort_kernel<<<1, 1024>>>(idx);
    prep_state<<<(BATCH * DIN / 4) / 256, 256>>>(state);
    prep_weights<<<(NGRP * DF * DIN + DF * DF + 255) / 256, 256>>>(W1, W2);
    gemm1_mma<<<dim3(518, 2), 256, SMEM_TOTAL>>>(b1);
    gemm2_mma<<<dim3(BATCH / 128, 2), 256, SMEM_TOTAL>>>(b2, action, idx, Wq);
    finishq<<<BATCH / 256, 256>>>(action, idx, bq, out);
}

// round 13
// speedup vs baseline: 3.7730x; 1.0706x over previous
#include <cuda_runtime.h>
#include <cuda_bf16.h>
#include <cstdint>

#define BATCH 65536
#define NGRP  6
#define DIN   512
#define DF    256
#define NOUT  18

// ---------------- scratch (static device globals) ----------------------------
__device__ int g_perm[BATCH];
__device__ int g_off[NGRP + 1];
__device__ __nv_bfloat16 g_sth[(size_t)(BATCH + 128) * DIN]; // state hi, PERMUTED order (+pad)
__device__ __nv_bfloat16 g_stl[(size_t)(BATCH + 128) * DIN]; // state lo, PERMUTED order
__device__ __nv_bfloat16 g_W1Th[NGRP * DF * DIN];     // [g][n][k] K-major hi
__device__ __nv_bfloat16 g_W1Tl[NGRP * DF * DIN];
__device__ __nv_bfloat16 g_W2Th[DF * DF];             // [n][k]
__device__ __nv_bfloat16 g_W2Tl[DF * DF];
__device__ __nv_bfloat16 g_h1h[(size_t)BATCH * DF];   // sorted-row order
__device__ __nv_bfloat16 g_h1l[(size_t)BATCH * DF];
__device__ float g_qpart[(size_t)BATCH * 4];          // partial Q dots

// ---------------- helpers ----------------------------------------------------
__device__ __forceinline__ uint32_t smem_u32(const void* p) {
    uint32_t a;
    asm("{ .reg .u64 t; cvta.to.shared.u64 t, %1; cvt.u32.u64 %0, t; }" : "=r"(a) : "l"(p));
    return a;
}
#define SWZ64(x) ((x) ^ (((x) >> 3) & 0x30))

__device__ __forceinline__ void cp16(uint32_t dst, const void* src) {
    asm volatile("cp.async.cg.shared.global [%0], [%1], 16;" :: "r"(dst), "l"(src));
}
#define CP_COMMIT() asm volatile("cp.async.commit_group;" ::: "memory")

__device__ __forceinline__ void ldsm4(uint32_t* r, uint32_t addr) {
    asm volatile("ldmatrix.sync.aligned.m8n8.x4.shared.b16 {%0,%1,%2,%3}, [%4];"
                 : "=r"(r[0]), "=r"(r[1]), "=r"(r[2]), "=r"(r[3]) : "r"(addr));
}
__device__ __forceinline__ void mma16816(float* d, const uint32_t* a, uint32_t b0, uint32_t b1) {
    asm volatile("mma.sync.aligned.m16n8k16.row.col.f32.bf16.bf16.f32 "
                 "{%0,%1,%2,%3}, {%4,%5,%6,%7}, {%8,%9}, {%0,%1,%2,%3};"
                 : "+f"(d[0]), "+f"(d[1]), "+f"(d[2]), "+f"(d[3])
                 : "r"(a[0]), "r"(a[1]), "r"(a[2]), "r"(a[3]), "r"(b0), "r"(b1));
}
__device__ __forceinline__ uint32_t pack_bf2(float a, float b) {
    __nv_bfloat162 t = __floats2bfloat162_rn(a, b);
    return *reinterpret_cast<uint32_t*>(&t);
}

// smem stage layout (bytes): A/B tiles are 128 rows x 32 k x bf16 = 8KB each
#define OFF_AH 0
#define OFF_AL 8192
#define OFF_BH 16384
#define OFF_BL 24576
#define STAGE_B 32768
#define NSTAGE 3
#define SMEM_TOTAL (NSTAGE * STAGE_B)

// per-warp compute of one 32-wide K chunk, warp tile 32(M) x 64(N):
// acc += Ah*Bh + Al*Bh + Ah*Bl  (fragments loaded once per k16 step)
__device__ __forceinline__ void mma_chunk(uint32_t sst, float (&acc)[2][8][4],
                                          int wm, int wn, int lane) {
    const int lr = lane & 7;
    const int lm = lane >> 3;
#pragma unroll
    for (int kk = 0; kk < 2; kk++) {
        uint32_t ah[8], al[8], bh[16], bl[16];
        const int kcA = kk * 16 + ((lm & 2) ? 8 : 0);
        const int rowA0 = wm * 32 + lr + ((lm & 1) ? 8 : 0);
#pragma unroll
        for (int mi = 0; mi < 2; mi++) {
            uint32_t off = SWZ64((uint32_t)((rowA0 + mi * 16) * 64 + kcA * 2));
            ldsm4(ah + mi * 4, sst + OFF_AH + off);
            ldsm4(al + mi * 4, sst + OFF_AL + off);
        }
        const int kcB = kk * 16 + ((lm & 1) ? 8 : 0);
        const int nB0 = wn * 64 + lr + ((lm & 2) ? 8 : 0);
#pragma unroll
        for (int bj = 0; bj < 4; bj++) {
            uint32_t off = SWZ64((uint32_t)((nB0 + bj * 16) * 64 + kcB * 2));
            ldsm4(bh + bj * 4, sst + OFF_BH + off);
        }
        // Ah*Bh and Al*Bh
#pragma unroll
        for (int mi = 0; mi < 2; mi++)
#pragma unroll
            for (int nj = 0; nj < 8; nj++) {
                int base = (nj >> 1) * 4 + (nj & 1) * 2;
                mma16816(acc[mi][nj], ah + mi * 4, bh[base], bh[base + 1]);
                mma16816(acc[mi][nj], al + mi * 4, bh[base], bh[base + 1]);
            }
#pragma unroll
        for (int bj = 0; bj < 4; bj++) {
            uint32_t off = SWZ64((uint32_t)((nB0 + bj * 16) * 64 + kcB * 2));
            ldsm4(bl + bj * 4, sst + OFF_BL + off);
        }
        // Ah*Bl
#pragma unroll
        for (int mi = 0; mi < 2; mi++)
#pragma unroll
            for (int nj = 0; nj < 8; nj++) {
                int base = (nj >> 1) * 4 + (nj & 1) * 2;
                mma16816(acc[mi][nj], ah + mi * 4, bl[base], bl[base + 1]);
            }
    }
}

// ---------------- 1. stable counting sort ------------------------------------
__global__ void __launch_bounds__(1024) sort_kernel(const int* __restrict__ idx)
{
    __shared__ int s[NGRP][1024];
    __shared__ int s_base[NGRP + 1];
    const int t = threadIdx.x;
    const int per = BATCH / 1024;
    const int base = t * per;

    int cnt[NGRP];
#pragma unroll
    for (int g = 0; g < NGRP; g++) cnt[g] = 0;
    for (int i = 0; i < per; i++) {
        int v = idx[base + i];
#pragma unroll
        for (int g = 0; g < NGRP; g++) cnt[g] += (v == g);
    }
#pragma unroll
    for (int g = 0; g < NGRP; g++) s[g][t] = cnt[g];
    __syncthreads();

    for (int d = 1; d < 1024; d <<= 1) {
        int v[NGRP];
        if (t >= d) {
#pragma unroll
            for (int g = 0; g < NGRP; g++) v[g] = s[g][t - d];
        }
        __syncthreads();
        if (t >= d) {
#pragma unroll
            for (int g = 0; g < NGRP; g++) s[g][t] += v[g];
        }
        __syncthreads();
    }

    if (t == 0) {
        int acc = 0;
#pragma unroll
        for (int g = 0; g < NGRP; g++) { s_base[g] = acc; acc += s[g][1023]; }
        s_base[NGRP] = acc;
        for (int g = 0; g <= NGRP; g++) g_off[g] = s_base[g];
    }
    __syncthreads();

    int pos[NGRP];
#pragma unroll
    for (int g = 0; g < NGRP; g++) pos[g] = s_base[g] + s[g][t] - cnt[g];

    for (int i = 0; i < per; i++) {
        int v = idx[base + i];
        int p = 0;
#pragma unroll
        for (int g = 0; g < NGRP; g++) if (v == g) p = pos[g]++;
        g_perm[p] = base + i;
    }
}

// ---------------- 2a. state: gather by perm + split fp32 -> bf16 hi/lo -------
__global__ void __launch_bounds__(256) prep_state(const float* __restrict__ state)
{
    size_t p = (size_t)blockIdx.x * 256 + threadIdx.x;   // float4 index (dest)
    const int row = (int)(p >> 7);                       // DIN/4 = 128 float4/row
    const int col = (int)(p & 127);
    const int src = __ldg(&g_perm[row]);
    float4 v = ((const float4*)state)[(size_t)src * 128 + col];
    float f[4] = { v.x, v.y, v.z, v.w };
    float hf[4], lf[4];
#pragma unroll
    for (int j = 0; j < 4; j++) {
        __nv_bfloat16 h = __float2bfloat16(f[j]);
        hf[j] = __bfloat162float(h);
        lf[j] = f[j] - hf[j];
    }
    uint2 uh = { pack_bf2(hf[0], hf[1]), pack_bf2(hf[2], hf[3]) };
    uint2 ul = { pack_bf2(lf[0], lf[1]), pack_bf2(lf[2], lf[3]) };
    ((uint2*)g_sth)[p] = uh;
    ((uint2*)g_stl)[p] = ul;
}

// ---------------- 2b. weight transpose + bf16 split --------------------------
__global__ void __launch_bounds__(256) prep_weights(const float* __restrict__ W1,
                                                    const float* __restrict__ W2)
{
    const int N1 = NGRP * DF * DIN;
    int t = blockIdx.x * 256 + threadIdx.x;
    if (t < N1) {
        int g = t / (DF * DIN);
        int r = t - g * DF * DIN;
        int n = r / DIN;
        int k = r - n * DIN;
        float x = W1[(size_t)g * DIN * DF + (size_t)k * DF + n];
        __nv_bfloat16 h = __float2bfloat16(x);
        g_W1Th[t] = h;
        g_W1Tl[t] = __float2bfloat16(x - __bfloat162float(h));
    } else if (t < N1 + DF * DF) {
        int r = t - N1;
        int n = r / DF;
        int k = r - n * DF;
        float x = W2[(size_t)k * DF + n];
        __nv_bfloat16 h = __float2bfloat16(x);
        g_W2Th[r] = h;
        g_W2Tl[r] = __float2bfloat16(x - __bfloat162float(h));
    }
}

// ---------------- 3. GEMM1: h1 = sigmoid(state_perm @ W1[g] + b1[g]) ---------
// tile 128(M) x 128(N), K-chunk 32, 256 threads, 3-stage cp.async, 2 CTAs/SM
__global__ void __launch_bounds__(256, 2) gemm1_mma(const float* __restrict__ b1)
{
    int bid = blockIdx.x;
    int g = -1, row_start = 0, row_end = 0, acct = 0;
#pragma unroll
    for (int gg = 0; gg < NGRP; gg++) {
        int c0 = g_off[gg], c1 = g_off[gg + 1];
        int nt = (c1 - c0 + 127) >> 7;
        if (g < 0 && bid < acct + nt) { g = gg; row_start = c0 + (bid - acct) * 128; row_end = c1; }
        acct += nt;
    }
    if (g < 0) return;
    const int n0 = blockIdx.y * 128;

    extern __shared__ __align__(1024) char smem[];
    const uint32_t sbase = smem_u32(smem);
    const int tid = threadIdx.x, wid = tid >> 5, lane = tid & 31;
    const int wm = wid >> 1, wn = wid & 1;

    const __nv_bfloat16* WH = g_W1Th + (size_t)(g * DF + n0) * DIN;
    const __nv_bfloat16* WL = g_W1Tl + (size_t)(g * DF + n0) * DIN;
    const __nv_bfloat16* AH = g_sth + (size_t)row_start * DIN;  // rows padded past BATCH
    const __nv_bfloat16* AL = g_stl + (size_t)row_start * DIN;
    const int seg = tid & 3, rt0 = tid >> 2;   // rt0 in 0..63

    float acc[2][8][4];
#pragma unroll
    for (int a = 0; a < 2; a++)
#pragma unroll
        for (int b = 0; b < 8; b++)
#pragma unroll
            for (int c = 0; c < 4; c++) acc[a][b][c] = 0.f;

    auto issue = [&](int c) {
        uint32_t sst = sbase + (uint32_t)(c % NSTAGE) * STAGE_B;
        const int k0 = c * 32;
#pragma unroll
        for (int it = 0; it < 2; it++) {
            int rt = rt0 + it * 64;
            size_t rb = (size_t)rt * DIN + k0 + seg * 8;
            uint32_t off = SWZ64((uint32_t)(rt * 64 + seg * 16));
            cp16(sst + OFF_AH + off, AH + rb);
            cp16(sst + OFF_AL + off, AL + rb);
        }
#pragma unroll
        for (int it = 0; it < 2; it++) {
            int rn = rt0 + it * 64;
            size_t rb = (size_t)rn * DIN + k0 + seg * 8;
            uint32_t off = SWZ64((uint32_t)(rn * 64 + seg * 16));
            cp16(sst + OFF_BH + off, WH + rb);
            cp16(sst + OFF_BL + off, WL + rb);
        }
        CP_COMMIT();
    };

    const int CH = DIN / 32;   // 16
    issue(0); issue(1);
    for (int c = 0; c < CH; c++) {
        if (c < CH - 1) {
            asm volatile("cp.async.wait_group 1;" ::: "memory");
        } else {
            asm volatile("cp.async.wait_group 0;" ::: "memory");
        }
        __syncthreads();
        if (c + 2 < CH) issue(c + 2);
        mma_chunk(sbase + (uint32_t)(c % NSTAGE) * STAGE_B, acc, wm, wn, lane);
    }

    // epilogue: bias + sigmoid + bf16 hi/lo split -> g_h1h/g_h1l
    const float* bb = b1 + g * DF + n0;
#pragma unroll
    for (int mi = 0; mi < 2; mi++) {
        int r1 = row_start + wm * 32 + mi * 16 + (lane >> 2);
        int r2 = r1 + 8;
#pragma unroll
        for (int nj = 0; nj < 8; nj++) {
            int n = wn * 64 + nj * 8 + (lane & 3) * 2;
            float* a = acc[mi][nj];
            if (r1 < row_end) {
                float s0 = 1.f / (1.f + __expf(-(a[0] + bb[n])));
                float s1 = 1.f / (1.f + __expf(-(a[1] + bb[n + 1])));
                float l0 = s0 - __bfloat162float(__float2bfloat16(s0));
                float l1 = s1 - __bfloat162float(__float2bfloat16(s1));
                *(uint32_t*)(g_h1h + (size_t)r1 * DF + n0 + n) = pack_bf2(s0, s1);
                *(uint32_t*)(g_h1l + (size_t)r1 * DF + n0 + n) = pack_bf2(l0, l1);
            }
            if (r2 < row_end) {
                float s0 = 1.f / (1.f + __expf(-(a[2] + bb[n])));
                float s1 = 1.f / (1.f + __expf(-(a[3] + bb[n + 1])));
                float l0 = s0 - __bfloat162float(__float2bfloat16(s0));
                float l1 = s1 - __bfloat162float(__float2bfloat16(s1));
                *(uint32_t*)(g_h1h + (size_t)r2 * DF + n0 + n) = pack_bf2(s0, s1);
                *(uint32_t*)(g_h1l + (size_t)r2 * DF + n0 + n) = pack_bf2(l0, l1);
            }
        }
    }
}

// ---------------- 4. GEMM2 + fused partial Q head ----------------------------
__global__ void __launch_bounds__(256, 2) gemm2_mma(const float* __restrict__ b2,
                                                    const int* __restrict__ action,
                                                    const int* __restrict__ idx,
                                                    const float* __restrict__ Wq)
{
    const int m0 = blockIdx.x * 128;
    const int n0 = blockIdx.y * 128;
    extern __shared__ __align__(1024) char smem[];
    const uint32_t sbase = smem_u32(smem);
    const int tid = threadIdx.x, wid = tid >> 5, lane = tid & 31;
    const int wm = wid >> 1, wn = wid & 1;
    const int seg = tid & 3, rt0 = tid >> 2;

    const __nv_bfloat16* WH = g_W2Th + (size_t)n0 * DF;
    const __nv_bfloat16* WL = g_W2Tl + (size_t)n0 * DF;

    float acc[2][8][4];
#pragma unroll
    for (int a = 0; a < 2; a++)
#pragma unroll
        for (int b = 0; b < 8; b++)
#pragma unroll
            for (int c = 0; c < 4; c++) acc[a][b][c] = 0.f;

    auto issue = [&](int c) {
        uint32_t sst = sbase + (uint32_t)(c % NSTAGE) * STAGE_B;
        const int k0 = c * 32;
#pragma unroll
        for (int it = 0; it < 2; it++) {
            int rt = rt0 + it * 64;
            size_t rb = (size_t)(m0 + rt) * DF + k0 + seg * 8;
            uint32_t off = SWZ64((uint32_t)(rt * 64 + seg * 16));
            cp16(sst + OFF_AH + off, g_h1h + rb);
            cp16(sst + OFF_AL + off, g_h1l + rb);
        }
#pragma unroll
        for (int it = 0; it < 2; it++) {
            int rn = rt0 + it * 64;
            size_t rb = (size_t)rn * DF + k0 + seg * 8;
            uint32_t off = SWZ64((uint32_t)(rn * 64 + seg * 16));
            cp16(sst + OFF_BH + off, WH + rb);
            cp16(sst + OFF_BL + off, WL + rb);
        }
        CP_COMMIT();
    };

    const int CH = DF / 32;    // 8
    issue(0); issue(1);
    for (int c = 0; c < CH; c++) {
        if (c < CH - 1) {
            asm volatile("cp.async.wait_group 1;" ::: "memory");
        } else {
            asm volatile("cp.async.wait_group 0;" ::: "memory");
        }
        __syncthreads();
        if (c + 2 < CH) issue(c + 2);
        mma_chunk(sbase + (uint32_t)(c % NSTAGE) * STAGE_B, acc, wm, wn, lane);
    }

    // fused epilogue: partial dot of relu(acc + b2) with Wq[idx,:,action]
    const int slot = blockIdx.y * 2 + wn;      // 0..3
#pragma unroll
    for (int mi = 0; mi < 2; mi++) {
        const int rA = m0 + wm * 32 + mi * 16 + (lane >> 2);
        const int rB = rA + 8;
        const float* wqA = Wq + (size_t)idx[rA] * DF * NOUT + action[rA];
        const float* wqB = Wq + (size_t)idx[rB] * DF * NOUT + action[rB];
        float pA = 0.f, pB = 0.f;
#pragma unroll
        for (int nj = 0; nj < 8; nj++) {
            int n = n0 + wn * 64 + nj * 8 + (lane & 3) * 2;
            float* a = acc[mi][nj];
            float b20 = b2[n], b21 = b2[n + 1];
            pA += fmaxf(a[0] + b20, 0.f) * wqA[(size_t)n * NOUT]
                + fmaxf(a[1] + b21, 0.f) * wqA[(size_t)(n + 1) * NOUT];
            pB += fmaxf(a[2] + b20, 0.f) * wqB[(size_t)n * NOUT]
                + fmaxf(a[3] + b21, 0.f) * wqB[(size_t)(n + 1) * NOUT];
        }
        pA += __shfl_xor_sync(0xFFFFFFFFu, pA, 1);
        pA += __shfl_xor_sync(0xFFFFFFFFu, pA, 2);
        pB += __shfl_xor_sync(0xFFFFFFFFu, pB, 1);
        pB += __shfl_xor_sync(0xFFFFFFFFu, pB, 2);
        if ((lane & 3) == 0) {
            g_qpart[(size_t)rA * 4 + slot] = pA;
            g_qpart[(size_t)rB * 4 + slot] = pB;
        }
    }
}

// ---------------- 5. finish: sum partials + bias + tanh ----------------------
__global__ void __launch_bounds__(256) finishq(const int* __restrict__ action,
                                               const int* __restrict__ idx,
                                               const float* __restrict__ bq,
                                               float* __restrict__ out)
{
    const int m = blockIdx.x * 256 + threadIdx.x;
    float4 p = ((const float4*)g_qpart)[m];
    const int gi = idx[m];
    const int ai = action[m];
    out[m] = tanhf(p.x + p.y + p.z + p.w + bq[gi * NOUT + ai]);
}

// ---------------- launcher ---------------------------------------------------
extern "C" void kernel_launch(void* const* d_in, const int* in_sizes, int n_in,
                              void* d_out, int out_size)
{
    const float* state  = (const float*)d_in[0];
    const int*   action = (const int*)d_in[1];
    const int*   idx    = (const int*)d_in[2];
    const float* W1     = (const float*)d_in[3];
    const float* b1     = (const float*)d_in[4];
    const float* W2     = (const float*)d_in[5];
    const float* b2     = (const float*)d_in[6];
    const float* Wq     = (const float*)d_in[7];
    const float* bq     = (const float*)d_in[8];
    float* out = (float*)d_out;

    cudaFuncSetAttribute(gemm1_mma, cudaFuncAttributeMaxDynamicSharedMemorySize, SMEM_TOTAL);
    cudaFuncSetAttribute(gemm2_mma, cudaFuncAttributeMaxDynamicSharedMemorySize, SMEM_TOTAL);

    sort_kernel<<<1, 1024>>>(idx);
    prep_state<<<(BATCH * DIN / 4) / 256, 256>>>(state);
    prep_weights<<<(NGRP * DF * DIN + DF * DF + 255) / 256, 256>>>(W1, W2);
    gemm1_mma<<<dim3(518, 2), 256, SMEM_TOTAL>>>(b1);
    gemm2_mma<<<dim3(BATCH / 128, 2), 256, SMEM_TOTAL>>>(b2, action, idx, Wq);
    finishq<<<BATCH / 256, 256>>>(action, idx, bq, out);
}

// round 16
// speedup vs baseline: 4.9936x; 1.3235x over previous
#include <cuda_runtime.h>
#include <cuda_bf16.h>
#include <cstdint>

#define BATCH 65536
#define NGRP  6
#define DIN   512
#define DF    256
#define NOUT  18

// ---------------- scratch (static device globals) ----------------------------
__device__ int g_perm[BATCH];
__device__ int g_off[NGRP + 1];
__device__ int g_bh[NGRP * 64];      // per-block bucket counts
__device__ int g_bbase[NGRP * 64];   // global scatter base per (bucket, block)
__device__ __nv_bfloat16 g_sth[(size_t)(BATCH + 128) * DIN]; // state hi, PERMUTED order (+pad)
__device__ __nv_bfloat16 g_stl[(size_t)(BATCH + 128) * DIN]; // state lo, PERMUTED order
__device__ __nv_bfloat16 g_W1Th[NGRP * DF * DIN];     // [g][n][k] K-major hi
__device__ __nv_bfloat16 g_W1Tl[NGRP * DF * DIN];
__device__ __nv_bfloat16 g_W2Th[DF * DF];             // [n][k]
__device__ __nv_bfloat16 g_W2Tl[DF * DF];
__device__ __nv_bfloat16 g_h1h[(size_t)BATCH * DF];   // sorted-row order
__device__ __nv_bfloat16 g_h1l[(size_t)BATCH * DF];
__device__ float g_qpart[(size_t)BATCH * 4];          // partial Q dots

// ---------------- helpers ----------------------------------------------------
__device__ __forceinline__ uint32_t smem_u32(const void* p) {
    uint32_t a;
    asm("{ .reg .u64 t; cvta.to.shared.u64 t, %1; cvt.u32.u64 %0, t; }" : "=r"(a) : "l"(p));
    return a;
}
#define SWZ64(x) ((x) ^ (((x) >> 3) & 0x30))

__device__ __forceinline__ void cp16(uint32_t dst, const void* src) {
    asm volatile("cp.async.cg.shared.global [%0], [%1], 16;" :: "r"(dst), "l"(src));
}
#define CP_COMMIT() asm volatile("cp.async.commit_group;" ::: "memory")

__device__ __forceinline__ void ldsm4(uint32_t* r, uint32_t addr) {
    asm volatile("ldmatrix.sync.aligned.m8n8.x4.shared.b16 {%0,%1,%2,%3}, [%4];"
                 : "=r"(r[0]), "=r"(r[1]), "=r"(r[2]), "=r"(r[3]) : "r"(addr));
}
__device__ __forceinline__ void mma16816(float* d, const uint32_t* a, uint32_t b0, uint32_t b1) {
    asm volatile("mma.sync.aligned.m16n8k16.row.col.f32.bf16.bf16.f32 "
                 "{%0,%1,%2,%3}, {%4,%5,%6,%7}, {%8,%9}, {%0,%1,%2,%3};"
                 : "+f"(d[0]), "+f"(d[1]), "+f"(d[2]), "+f"(d[3])
                 : "r"(a[0]), "r"(a[1]), "r"(a[2]), "r"(a[3]), "r"(b0), "r"(b1));
}
__device__ __forceinline__ uint32_t pack_bf2(float a, float b) {
    __nv_bfloat162 t = __floats2bfloat162_rn(a, b);
    return *reinterpret_cast<uint32_t*>(&t);
}

// smem stage layout (bytes): A/B tiles are 128 rows x 32 k x bf16 = 8KB each
#define OFF_AH 0
#define OFF_AL 8192
#define OFF_BH 16384
#define OFF_BL 24576
#define STAGE_B 32768
#define NSTAGE 3
#define SMEM_TOTAL (NSTAGE * STAGE_B)

// per-warp compute of one 32-wide K chunk, warp tile 32(M) x 64(N):
// acc += Ah*Bh + Al*Bh + Ah*Bl  (fragments loaded once per k16 step)
__device__ __forceinline__ void mma_chunk(uint32_t sst, float (&acc)[2][8][4],
                                          int wm, int wn, int lane) {
    const int lr = lane & 7;
    const int lm = lane >> 3;
#pragma unroll
    for (int kk = 0; kk < 2; kk++) {
        uint32_t ah[8], al[8], bh[16], bl[16];
        const int kcA = kk * 16 + ((lm & 2) ? 8 : 0);
        const int rowA0 = wm * 32 + lr + ((lm & 1) ? 8 : 0);
#pragma unroll
        for (int mi = 0; mi < 2; mi++) {
            uint32_t off = SWZ64((uint32_t)((rowA0 + mi * 16) * 64 + kcA * 2));
            ldsm4(ah + mi * 4, sst + OFF_AH + off);
            ldsm4(al + mi * 4, sst + OFF_AL + off);
        }
        const int kcB = kk * 16 + ((lm & 1) ? 8 : 0);
        const int nB0 = wn * 64 + lr + ((lm & 2) ? 8 : 0);
#pragma unroll
        for (int bj = 0; bj < 4; bj++) {
            uint32_t off = SWZ64((uint32_t)((nB0 + bj * 16) * 64 + kcB * 2));
            ldsm4(bh + bj * 4, sst + OFF_BH + off);
        }
#pragma unroll
        for (int mi = 0; mi < 2; mi++)
#pragma unroll
            for (int nj = 0; nj < 8; nj++) {
                int base = (nj >> 1) * 4 + (nj & 1) * 2;
                mma16816(acc[mi][nj], ah + mi * 4, bh[base], bh[base + 1]);
                mma16816(acc[mi][nj], al + mi * 4, bh[base], bh[base + 1]);
            }
#pragma unroll
        for (int bj = 0; bj < 4; bj++) {
            uint32_t off = SWZ64((uint32_t)((nB0 + bj * 16) * 64 + kcB * 2));
            ldsm4(bl + bj * 4, sst + OFF_BL + off);
        }
#pragma unroll
        for (int mi = 0; mi < 2; mi++)
#pragma unroll
            for (int nj = 0; nj < 8; nj++) {
                int base = (nj >> 1) * 4 + (nj & 1) * 2;
                mma16816(acc[mi][nj], ah + mi * 4, bl[base], bl[base + 1]);
            }
    }
}

// ---------------- 1. parallel stable bucket sort (3 phases) ------------------
// phase 1: per-block histograms (64 blocks x 256 threads x 4 elems)
__global__ void __launch_bounds__(256) sort_count(const int* __restrict__ idx)
{
    __shared__ int sh[NGRP];
    const int t = threadIdx.x, b = blockIdx.x;
    if (t < NGRP) sh[t] = 0;
    __syncthreads();
    int4 v = *(const int4*)(idx + b * 1024 + t * 4);
    int e[4] = { v.x, v.y, v.z, v.w };
#pragma unroll
    for (int g = 0; g < NGRP; g++) {
        int c = (e[0] == g) + (e[1] == g) + (e[2] == g) + (e[3] == g);
        if (c) atomicAdd(&sh[g], c);
    }
    __syncthreads();
    if (t < NGRP) g_bh[t * 64 + b] = sh[t];
}

// phase 2: tiny scan -> per-(bucket,block) global bases + group offsets
__global__ void __launch_bounds__(32) sort_scan()
{
    __shared__ int tot[NGRP];
    const int t = threadIdx.x;
    if (t < NGRP) {
        int acc = 0;
        for (int b = 0; b < 64; b++) { int v = g_bh[t * 64 + b]; g_bbase[t * 64 + b] = acc; acc += v; }
        tot[t] = acc;
    }
    __syncthreads();
    if (t == 0) {
        int acc = 0;
        for (int g = 0; g < NGRP; g++) { g_off[g] = acc; acc += tot[g]; }
        g_off[NGRP] = acc;
    }
    __syncthreads();
    if (t < NGRP) {
        int base = g_off[t];
        for (int b = 0; b < 64; b++) g_bbase[t * 64 + b] += base;
    }
}

// phase 3: stable scatter (thread t covers contiguous elems -> stability)
__global__ void __launch_bounds__(256) sort_scatter(const int* __restrict__ idx)
{
    __shared__ int s[NGRP][256];
    const int t = threadIdx.x, b = blockIdx.x;
    const int base = b * 1024 + t * 4;
    int4 v = *(const int4*)(idx + base);
    int e[4] = { v.x, v.y, v.z, v.w };
    int cnt[NGRP];
#pragma unroll
    for (int g = 0; g < NGRP; g++) {
        cnt[g] = (e[0] == g) + (e[1] == g) + (e[2] == g) + (e[3] == g);
        s[g][t] = cnt[g];
    }
    __syncthreads();
    for (int d = 1; d < 256; d <<= 1) {
        int tmp[NGRP];
        if (t >= d) {
#pragma unroll
            for (int g = 0; g < NGRP; g++) tmp[g] = s[g][t - d];
        }
        __syncthreads();
        if (t >= d) {
#pragma unroll
            for (int g = 0; g < NGRP; g++) s[g][t] += tmp[g];
        }
        __syncthreads();
    }
    int pos[NGRP];
#pragma unroll
    for (int g = 0; g < NGRP; g++) pos[g] = g_bbase[g * 64 + b] + s[g][t] - cnt[g];
#pragma unroll
    for (int i = 0; i < 4; i++) {
        int p = 0;
#pragma unroll
        for (int g = 0; g < NGRP; g++) if (e[i] == g) p = pos[g]++;
        g_perm[p] = base + i;
    }
}

// ---------------- 2a. state: gather by perm + split fp32 -> bf16 hi/lo -------
__global__ void __launch_bounds__(256) prep_state(const float* __restrict__ state)
{
    size_t p = (size_t)blockIdx.x * 256 + threadIdx.x;   // float4 index (dest)
    const int row = (int)(p >> 7);                       // DIN/4 = 128 float4/row
    const int col = (int)(p & 127);
    const int src = __ldg(&g_perm[row]);
    float4 v = ((const float4*)state)[(size_t)src * 128 + col];
    float f[4] = { v.x, v.y, v.z, v.w };
    float hf[4], lf[4];
#pragma unroll
    for (int j = 0; j < 4; j++) {
        __nv_bfloat16 h = __float2bfloat16(f[j]);
        hf[j] = __bfloat162float(h);
        lf[j] = f[j] - hf[j];
    }
    uint2 uh = { pack_bf2(hf[0], hf[1]), pack_bf2(hf[2], hf[3]) };
    uint2 ul = { pack_bf2(lf[0], lf[1]), pack_bf2(lf[2], lf[3]) };
    ((uint2*)g_sth)[p] = uh;
    ((uint2*)g_stl)[p] = ul;
}

// ---------------- 2b. weight transpose + split, coalesced via smem tiles -----
// z in [0,NGRP): W1 expert z ([512][256]); z == NGRP: W2 ([256][256])
__global__ void __launch_bounds__(256) prep_weights(const float* __restrict__ W1,
                                                    const float* __restrict__ W2)
{
    __shared__ float tile[32][33];
    const int z = blockIdx.z;
    const int k0 = blockIdx.x * 32, n0 = blockIdx.y * 32;
    const int tx = threadIdx.x & 31, ty = threadIdx.x >> 5;   // block 256 = 32x8

    const bool isW2 = (z == NGRP);
    if (isW2 && k0 >= DF) return;
    const float* src = isW2 ? W2 : (W1 + (size_t)z * DIN * DF);
    const int ldk_out = isW2 ? DF : DIN;
    __nv_bfloat16* dh = isW2 ? g_W2Th : (g_W1Th + (size_t)z * DF * DIN);
    __nv_bfloat16* dl = isW2 ? g_W2Tl : (g_W1Tl + (size_t)z * DF * DIN);

#pragma unroll
    for (int i = 0; i < 4; i++) {
        int k = k0 + ty + i * 8;
        tile[ty + i * 8][tx] = src[(size_t)k * DF + n0 + tx];   // coalesced in n
    }
    __syncthreads();
#pragma unroll
    for (int i = 0; i < 4; i++) {
        int n = n0 + ty + i * 8;
        float x = tile[tx][ty + i * 8];
        __nv_bfloat16 h = __float2bfloat16(x);
        size_t o = (size_t)n * ldk_out + k0 + tx;               // coalesced in k
        dh[o] = h;
        dl[o] = __float2bfloat16(x - __bfloat162float(h));
    }
}

// ---------------- 3. GEMM1: h1 = sigmoid(state_perm @ W1[g] + b1[g]) ---------
// tile 128(M) x 128(N), K-chunk 32, 256 threads, 3-stage cp.async, 2 CTAs/SM
__global__ void __launch_bounds__(256, 2) gemm1_mma(const float* __restrict__ b1)
{
    int bid = blockIdx.x;
    int g = -1, row_start = 0, row_end = 0, acct = 0;
#pragma unroll
    for (int gg = 0; gg < NGRP; gg++) {
        int c0 = g_off[gg], c1 = g_off[gg + 1];
        int nt = (c1 - c0 + 127) >> 7;
        if (g < 0 && bid < acct + nt) { g = gg; row_start = c0 + (bid - acct) * 128; row_end = c1; }
        acct += nt;
    }
    if (g < 0) return;
    const int n0 = blockIdx.y * 128;

    extern __shared__ __align__(1024) char smem[];
    const uint32_t sbase = smem_u32(smem);
    const int tid = threadIdx.x, wid = tid >> 5, lane = tid & 31;
    const int wm = wid >> 1, wn = wid & 1;

    const __nv_bfloat16* WH = g_W1Th + (size_t)(g * DF + n0) * DIN;
    const __nv_bfloat16* WL = g_W1Tl + (size_t)(g * DF + n0) * DIN;
    const __nv_bfloat16* AH = g_sth + (size_t)row_start * DIN;
    const __nv_bfloat16* AL = g_stl + (size_t)row_start * DIN;
    const int seg = tid & 3, rt0 = tid >> 2;   // rt0 in 0..63

    float acc[2][8][4];
#pragma unroll
    for (int a = 0; a < 2; a++)
#pragma unroll
        for (int b = 0; b < 8; b++)
#pragma unroll
            for (int c = 0; c < 4; c++) acc[a][b][c] = 0.f;

    auto issue = [&](int c) {
        uint32_t sst = sbase + (uint32_t)(c % NSTAGE) * STAGE_B;
        const int k0 = c * 32;
#pragma unroll
        for (int it = 0; it < 2; it++) {
            int rt = rt0 + it * 64;
            size_t rb = (size_t)rt * DIN + k0 + seg * 8;
            uint32_t off = SWZ64((uint32_t)(rt * 64 + seg * 16));
            cp16(sst + OFF_AH + off, AH + rb);
            cp16(sst + OFF_AL + off, AL + rb);
        }
#pragma unroll
        for (int it = 0; it < 2; it++) {
            int rn = rt0 + it * 64;
            size_t rb = (size_t)rn * DIN + k0 + seg * 8;
            uint32_t off = SWZ64((uint32_t)(rn * 64 + seg * 16));
            cp16(sst + OFF_BH + off, WH + rb);
            cp16(sst + OFF_BL + off, WL + rb);
        }
        CP_COMMIT();
    };

    const int CH = DIN / 32;   // 16
    issue(0); issue(1);
    for (int c = 0; c < CH; c++) {
        if (c < CH - 1) {
            asm volatile("cp.async.wait_group 1;" ::: "memory");
        } else {
            asm volatile("cp.async.wait_group 0;" ::: "memory");
        }
        __syncthreads();
        if (c + 2 < CH) issue(c + 2);
        mma_chunk(sbase + (uint32_t)(c % NSTAGE) * STAGE_B, acc, wm, wn, lane);
    }

    // epilogue: bias + sigmoid + bf16 hi/lo split -> g_h1h/g_h1l
    const float* bb = b1 + g * DF + n0;
#pragma unroll
    for (int mi = 0; mi < 2; mi++) {
        int r1 = row_start + wm * 32 + mi * 16 + (lane >> 2);
        int r2 = r1 + 8;
#pragma unroll
        for (int nj = 0; nj < 8; nj++) {
            int n = wn * 64 + nj * 8 + (lane & 3) * 2;
            float* a = acc[mi][nj];
            if (r1 < row_end) {
                float s0 = 1.f / (1.f + __expf(-(a[0] + bb[n])));
                float s1 = 1.f / (1.f + __expf(-(a[1] + bb[n + 1])));
                float l0 = s0 - __bfloat162float(__float2bfloat16(s0));
                float l1 = s1 - __bfloat162float(__float2bfloat16(s1));
                *(uint32_t*)(g_h1h + (size_t)r1 * DF + n0 + n) = pack_bf2(s0, s1);
                *(uint32_t*)(g_h1l + (size_t)r1 * DF + n0 + n) = pack_bf2(l0, l1);
            }
            if (r2 < row_end) {
                float s0 = 1.f / (1.f + __expf(-(a[2] + bb[n])));
                float s1 = 1.f / (1.f + __expf(-(a[3] + bb[n + 1])));
                float l0 = s0 - __bfloat162float(__float2bfloat16(s0));
                float l1 = s1 - __bfloat162float(__float2bfloat16(s1));
                *(uint32_t*)(g_h1h + (size_t)r2 * DF + n0 + n) = pack_bf2(s0, s1);
                *(uint32_t*)(g_h1l + (size_t)r2 * DF + n0 + n) = pack_bf2(l0, l1);
            }
        }
    }
}

// ---------------- 4. GEMM2 + fused partial Q head ----------------------------
__global__ void __launch_bounds__(256, 2) gemm2_mma(const float* __restrict__ b2,
                                                    const int* __restrict__ action,
                                                    const int* __restrict__ idx,
                                                    const float* __restrict__ Wq)
{
    const int m0 = blockIdx.x * 128;
    const int n0 = blockIdx.y * 128;
    extern __shared__ __align__(1024) char smem[];
    const uint32_t sbase = smem_u32(smem);
    const int tid = threadIdx.x, wid = tid >> 5, lane = tid & 31;
    const int wm = wid >> 1, wn = wid & 1;
    const int seg = tid & 3, rt0 = tid >> 2;

    const __nv_bfloat16* WH = g_W2Th + (size_t)n0 * DF;
    const __nv_bfloat16* WL = g_W2Tl + (size_t)n0 * DF;

    float acc[2][8][4];
#pragma unroll
    for (int a = 0; a < 2; a++)
#pragma unroll
        for (int b = 0; b < 8; b++)
#pragma unroll
            for (int c = 0; c < 4; c++) acc[a][b][c] = 0.f;

    auto issue = [&](int c) {
        uint32_t sst = sbase + (uint32_t)(c % NSTAGE) * STAGE_B;
        const int k0 = c * 32;
#pragma unroll
        for (int it = 0; it < 2; it++) {
            int rt = rt0 + it * 64;
            size_t rb = (size_t)(m0 + rt) * DF + k0 + seg * 8;
            uint32_t off = SWZ64((uint32_t)(rt * 64 + seg * 16));
            cp16(sst + OFF_AH + off, g_h1h + rb);
            cp16(sst + OFF_AL + off, g_h1l + rb);
        }
#pragma unroll
        for (int it = 0; it < 2; it++) {
            int rn = rt0 + it * 64;
            size_t rb = (size_t)rn * DF + k0 + seg * 8;
            uint32_t off = SWZ64((uint32_t)(rn * 64 + seg * 16));
            cp16(sst + OFF_BH + off, WH + rb);
            cp16(sst + OFF_BL + off, WL + rb);
        }
        CP_COMMIT();
    };

    const int CH = DF / 32;    // 8
    issue(0); issue(1);
    for (int c = 0; c < CH; c++) {
        if (c < CH - 1) {
            asm volatile("cp.async.wait_group 1;" ::: "memory");
        } else {
            asm volatile("cp.async.wait_group 0;" ::: "memory");
        }
        __syncthreads();
        if (c + 2 < CH) issue(c + 2);
        mma_chunk(sbase + (uint32_t)(c % NSTAGE) * STAGE_B, acc, wm, wn, lane);
    }

    // fused epilogue: partial dot of relu(acc + b2) with Wq[idx,:,action]
    const int slot = blockIdx.y * 2 + wn;      // 0..3
#pragma unroll
    for (int mi = 0; mi < 2; mi++) {
        const int rA = m0 + wm * 32 + mi * 16 + (lane >> 2);
        const int rB = rA + 8;
        const float* wqA = Wq + (size_t)idx[rA] * DF * NOUT + action[rA];
        const float* wqB = Wq + (size_t)idx[rB] * DF * NOUT + action[rB];
        float pA = 0.f, pB = 0.f;
#pragma unroll
        for (int nj = 0; nj < 8; nj++) {
            int n = n0 + wn * 64 + nj * 8 + (lane & 3) * 2;
            float* a = acc[mi][nj];
            float b20 = b2[n], b21 = b2[n + 1];
            pA += fmaxf(a[0] + b20, 0.f) * wqA[(size_t)n * NOUT]
                + fmaxf(a[1] + b21, 0.f) * wqA[(size_t)(n + 1) * NOUT];
            pB += fmaxf(a[2] + b20, 0.f) * wqB[(size_t)n * NOUT]
                + fmaxf(a[3] + b21, 0.f) * wqB[(size_t)(n + 1) * NOUT];
        }
        pA += __shfl_xor_sync(0xFFFFFFFFu, pA, 1);
        pA += __shfl_xor_sync(0xFFFFFFFFu, pA, 2);
        pB += __shfl_xor_sync(0xFFFFFFFFu, pB, 1);
        pB += __shfl_xor_sync(0xFFFFFFFFu, pB, 2);
        if ((lane & 3) == 0) {
            g_qpart[(size_t)rA * 4 + slot] = pA;
            g_qpart[(size_t)rB * 4 + slot] = pB;
        }
    }
}

// ---------------- 5. finish: sum partials + bias + tanh ----------------------
__global__ void __launch_bounds__(256) finishq(const int* __restrict__ action,
                                               const int* __restrict__ idx,
                                               const float* __restrict__ bq,
                                               float* __restrict__ out)
{
    const int m = blockIdx.x * 256 + threadIdx.x;
    float4 p = ((const float4*)g_qpart)[m];
    const int gi = idx[m];
    const int ai = action[m];
    out[m] = tanhf(p.x + p.y + p.z + p.w + bq[gi * NOUT + ai]);
}

// ---------------- launcher ---------------------------------------------------
extern "C" void kernel_launch(void* const* d_in, const int* in_sizes, int n_in,
                              void* d_out, int out_size)
{
    const float* state  = (const float*)d_in[0];
    const int*   action = (const int*)d_in[1];
    const int*   idx    = (const int*)d_in[2];
    const float* W1     = (const float*)d_in[3];
    const float* b1     = (const float*)d_in[4];
    const float* W2     = (const float*)d_in[5];
    const float* b2     = (const float*)d_in[6];
    const float* Wq     = (const float*)d_in[7];
    const float* bq     = (const float*)d_in[8];
    float* out = (float*)d_out;

    cudaFuncSetAttribute(gemm1_mma, cudaFuncAttributeMaxDynamicSharedMemorySize, SMEM_TOTAL);
    cudaFuncSetAttribute(gemm2_mma, cudaFuncAttributeMaxDynamicSharedMemorySize, SMEM_TOTAL);

    sort_count<<<64, 256>>>(idx);
    sort_scan<<<1, 32>>>();
    prep_weights<<<dim3(DIN / 32, DF / 32, NGRP + 1), 256>>>(W1, W2);
    sort_scatter<<<64, 256>>>(idx);
    prep_state<<<(BATCH * DIN / 4) / 256, 256>>>(state);
    gemm1_mma<<<dim3(518, 2), 256, SMEM_TOTAL>>>(b1);
    gemm2_mma<<<dim3(BATCH / 128, 2), 256, SMEM_TOTAL>>>(b2, action, idx, Wq);
    finishq<<<BATCH / 256, 256>>>(action, idx, bq, out);
}

// round 17
// speedup vs baseline: 5.2561x; 1.0526x over previous
#include <cuda_runtime.h>
#include <cuda_bf16.h>
#include <cstdint>

#define BATCH 65536
#define NGRP  6
#define DIN   512
#define DF    256
#define NOUT  18

// ---------------- scratch (static device globals) ----------------------------
__device__ int g_perm[BATCH];
__device__ int g_off[NGRP + 1];
__device__ int g_bh[NGRP * 64];      // per-block bucket counts
__device__ int g_bbase[NGRP * 64];   // global scatter base per (bucket, block)
__device__ __nv_bfloat16 g_sth[(size_t)(BATCH + 128) * DIN]; // state hi, PERMUTED order (+pad)
__device__ __nv_bfloat16 g_stl[(size_t)(BATCH + 128) * DIN]; // state lo, PERMUTED order
__device__ __nv_bfloat16 g_W1Th[NGRP * DF * DIN];     // [g][n][k] K-major hi
__device__ __nv_bfloat16 g_W1Tl[NGRP * DF * DIN];
__device__ __nv_bfloat16 g_W2Th[DF * DF];             // [n][k]
__device__ __nv_bfloat16 g_W2Tl[DF * DF];
__device__ __nv_bfloat16 g_h1h[(size_t)BATCH * DF];   // sorted-row order
__device__ __nv_bfloat16 g_h1l[(size_t)BATCH * DF];
__device__ float g_qpart[(size_t)BATCH * 4];          // partial Q dots

// ---------------- helpers ----------------------------------------------------
__device__ __forceinline__ uint32_t smem_u32(const void* p) {
    uint32_t a;
    asm("{ .reg .u64 t; cvta.to.shared.u64 t, %1; cvt.u32.u64 %0, t; }" : "=r"(a) : "l"(p));
    return a;
}
#define SWZ64(x) ((x) ^ (((x) >> 3) & 0x30))

__device__ __forceinline__ void cp16(uint32_t dst, const void* src) {
    asm volatile("cp.async.cg.shared.global [%0], [%1], 16;" :: "r"(dst), "l"(src));
}
#define CP_COMMIT() asm volatile("cp.async.commit_group;" ::: "memory")

__device__ __forceinline__ void ldsm4(uint32_t* r, uint32_t addr) {
    asm volatile("ldmatrix.sync.aligned.m8n8.x4.shared.b16 {%0,%1,%2,%3}, [%4];"
                 : "=r"(r[0]), "=r"(r[1]), "=r"(r[2]), "=r"(r[3]) : "r"(addr));
}
__device__ __forceinline__ void mma16816(float* d, const uint32_t* a, uint32_t b0, uint32_t b1) {
    asm volatile("mma.sync.aligned.m16n8k16.row.col.f32.bf16.bf16.f32 "
                 "{%0,%1,%2,%3}, {%4,%5,%6,%7}, {%8,%9}, {%0,%1,%2,%3};"
                 : "+f"(d[0]), "+f"(d[1]), "+f"(d[2]), "+f"(d[3])
                 : "r"(a[0]), "r"(a[1]), "r"(a[2]), "r"(a[3]), "r"(b0), "r"(b1));
}
__device__ __forceinline__ uint32_t pack_bf2(float a, float b) {
    __nv_bfloat162 t = __floats2bfloat162_rn(a, b);
    return *reinterpret_cast<uint32_t*>(&t);
}

// smem stage layout (bytes): A/B tiles are 128 rows x 32 k x bf16 = 8KB each
#define OFF_AH 0
#define OFF_AL 8192
#define OFF_BH 16384
#define OFF_BL 24576
#define STAGE_B 32768
#define NSTAGE 3
#define SMEM_TOTAL (NSTAGE * STAGE_B)

// per-warp compute of one 32-wide K chunk, warp tile 32(M) x 64(N):
// acc += Ah*Bh + Al*Bh + Ah*Bl  (fragments loaded once per k16 step)
__device__ __forceinline__ void mma_chunk(uint32_t sst, float (&acc)[2][8][4],
                                          int wm, int wn, int lane) {
    const int lr = lane & 7;
    const int lm = lane >> 3;
#pragma unroll
    for (int kk = 0; kk < 2; kk++) {
        uint32_t ah[8], al[8], bh[16], bl[16];
        const int kcA = kk * 16 + ((lm & 2) ? 8 : 0);
        const int rowA0 = wm * 32 + lr + ((lm & 1) ? 8 : 0);
#pragma unroll
        for (int mi = 0; mi < 2; mi++) {
            uint32_t off = SWZ64((uint32_t)((rowA0 + mi * 16) * 64 + kcA * 2));
            ldsm4(ah + mi * 4, sst + OFF_AH + off);
            ldsm4(al + mi * 4, sst + OFF_AL + off);
        }
        const int kcB = kk * 16 + ((lm & 1) ? 8 : 0);
        const int nB0 = wn * 64 + lr + ((lm & 2) ? 8 : 0);
#pragma unroll
        for (int bj = 0; bj < 4; bj++) {
            uint32_t off = SWZ64((uint32_t)((nB0 + bj * 16) * 64 + kcB * 2));
            ldsm4(bh + bj * 4, sst + OFF_BH + off);
        }
#pragma unroll
        for (int mi = 0; mi < 2; mi++)
#pragma unroll
            for (int nj = 0; nj < 8; nj++) {
                int base = (nj >> 1) * 4 + (nj & 1) * 2;
                mma16816(acc[mi][nj], ah + mi * 4, bh[base], bh[base + 1]);
                mma16816(acc[mi][nj], al + mi * 4, bh[base], bh[base + 1]);
            }
#pragma unroll
        for (int bj = 0; bj < 4; bj++) {
            uint32_t off = SWZ64((uint32_t)((nB0 + bj * 16) * 64 + kcB * 2));
            ldsm4(bl + bj * 4, sst + OFF_BL + off);
        }
#pragma unroll
        for (int mi = 0; mi < 2; mi++)
#pragma unroll
            for (int nj = 0; nj < 8; nj++) {
                int base = (nj >> 1) * 4 + (nj & 1) * 2;
                mma16816(acc[mi][nj], ah + mi * 4, bl[base], bl[base + 1]);
            }
    }
}

// ---------------- 1. parallel stable bucket sort (3 phases) ------------------
__global__ void __launch_bounds__(256) sort_count(const int* __restrict__ idx)
{
    __shared__ int sh[NGRP];
    const int t = threadIdx.x, b = blockIdx.x;
    if (t < NGRP) sh[t] = 0;
    __syncthreads();
    int4 v = *(const int4*)(idx + b * 1024 + t * 4);
    int e[4] = { v.x, v.y, v.z, v.w };
#pragma unroll
    for (int g = 0; g < NGRP; g++) {
        int c = (e[0] == g) + (e[1] == g) + (e[2] == g) + (e[3] == g);
        if (c) atomicAdd(&sh[g], c);
    }
    __syncthreads();
    if (t < NGRP) g_bh[t * 64 + b] = sh[t];
}

__global__ void __launch_bounds__(32) sort_scan()
{
    __shared__ int tot[NGRP];
    const int t = threadIdx.x;
    if (t < NGRP) {
        int acc = 0;
        for (int b = 0; b < 64; b++) { int v = g_bh[t * 64 + b]; g_bbase[t * 64 + b] = acc; acc += v; }
        tot[t] = acc;
    }
    __syncthreads();
    if (t == 0) {
        int acc = 0;
        for (int g = 0; g < NGRP; g++) { g_off[g] = acc; acc += tot[g]; }
        g_off[NGRP] = acc;
    }
    __syncthreads();
    if (t < NGRP) {
        int base = g_off[t];
        for (int b = 0; b < 64; b++) g_bbase[t * 64 + b] += base;
    }
}

__global__ void __launch_bounds__(256) sort_scatter(const int* __restrict__ idx)
{
    __shared__ int s[NGRP][256];
    const int t = threadIdx.x, b = blockIdx.x;
    const int base = b * 1024 + t * 4;
    int4 v = *(const int4*)(idx + base);
    int e[4] = { v.x, v.y, v.z, v.w };
    int cnt[NGRP];
#pragma unroll
    for (int g = 0; g < NGRP; g++) {
        cnt[g] = (e[0] == g) + (e[1] == g) + (e[2] == g) + (e[3] == g);
        s[g][t] = cnt[g];
    }
    __syncthreads();
    for (int d = 1; d < 256; d <<= 1) {
        int tmp[NGRP];
        if (t >= d) {
#pragma unroll
            for (int g = 0; g < NGRP; g++) tmp[g] = s[g][t - d];
        }
        __syncthreads();
        if (t >= d) {
#pragma unroll
            for (int g = 0; g < NGRP; g++) s[g][t] += tmp[g];
        }
        __syncthreads();
    }
    int pos[NGRP];
#pragma unroll
    for (int g = 0; g < NGRP; g++) pos[g] = g_bbase[g * 64 + b] + s[g][t] - cnt[g];
#pragma unroll
    for (int i = 0; i < 4; i++) {
        int p = 0;
#pragma unroll
        for (int g = 0; g < NGRP; g++) if (e[i] == g) p = pos[g]++;
        g_perm[p] = base + i;
    }
}

// ---------------- 2a. state: gather by perm + split fp32 -> bf16 hi/lo -------
// 8 floats per thread; writes one uint4 (hi) + one uint4 (lo)
__global__ void __launch_bounds__(256) prep_state(const float* __restrict__ state)
{
    size_t p8 = (size_t)blockIdx.x * 256 + threadIdx.x;  // 8-float group index
    const int row = (int)(p8 >> 6);                      // 64 groups per row
    const int col = (int)(p8 & 63) * 8;
    const int src = __ldg(&g_perm[row]);
    const float* sp = state + (size_t)src * DIN + col;
    float4 v0 = *(const float4*)(sp);
    float4 v1 = *(const float4*)(sp + 4);
    float f[8] = { v0.x, v0.y, v0.z, v0.w, v1.x, v1.y, v1.z, v1.w };
    float hf[8], lf[8];
#pragma unroll
    for (int j = 0; j < 8; j++) {
        __nv_bfloat16 h = __float2bfloat16(f[j]);
        hf[j] = __bfloat162float(h);
        lf[j] = f[j] - hf[j];
    }
    uint4 uh = { pack_bf2(hf[0], hf[1]), pack_bf2(hf[2], hf[3]),
                 pack_bf2(hf[4], hf[5]), pack_bf2(hf[6], hf[7]) };
    uint4 ul = { pack_bf2(lf[0], lf[1]), pack_bf2(lf[2], lf[3]),
                 pack_bf2(lf[4], lf[5]), pack_bf2(lf[6], lf[7]) };
    ((uint4*)g_sth)[p8] = uh;
    ((uint4*)g_stl)[p8] = ul;
}

// ---------------- 2b. weight transpose + split, coalesced via smem tiles -----
__global__ void __launch_bounds__(256) prep_weights(const float* __restrict__ W1,
                                                    const float* __restrict__ W2)
{
    __shared__ float tile[32][33];
    const int z = blockIdx.z;
    const int k0 = blockIdx.x * 32, n0 = blockIdx.y * 32;
    const int tx = threadIdx.x & 31, ty = threadIdx.x >> 5;   // block 256 = 32x8

    const bool isW2 = (z == NGRP);
    if (isW2 && k0 >= DF) return;
    const float* src = isW2 ? W2 : (W1 + (size_t)z * DIN * DF);
    const int ldk_out = isW2 ? DF : DIN;
    __nv_bfloat16* dh = isW2 ? g_W2Th : (g_W1Th + (size_t)z * DF * DIN);
    __nv_bfloat16* dl = isW2 ? g_W2Tl : (g_W1Tl + (size_t)z * DF * DIN);

#pragma unroll
    for (int i = 0; i < 4; i++) {
        int k = k0 + ty + i * 8;
        tile[ty + i * 8][tx] = src[(size_t)k * DF + n0 + tx];
    }
    __syncthreads();
#pragma unroll
    for (int i = 0; i < 4; i++) {
        int n = n0 + ty + i * 8;
        float x = tile[tx][ty + i * 8];
        __nv_bfloat16 h = __float2bfloat16(x);
        size_t o = (size_t)n * ldk_out + k0 + tx;
        dh[o] = h;
        dl[o] = __float2bfloat16(x - __bfloat162float(h));
    }
}

// ---------------- 3. GEMM1: h1 = sigmoid(state_perm @ W1[g] + b1[g]) ---------
// grid (2, 518): N-tile is the FAST dim so both N-tiles sharing A run adjacent
__global__ void __launch_bounds__(256, 2) gemm1_mma(const float* __restrict__ b1)
{
    int bid = blockIdx.y;
    int g = -1, row_start = 0, row_end = 0, acct = 0;
#pragma unroll
    for (int gg = 0; gg < NGRP; gg++) {
        int c0 = g_off[gg], c1 = g_off[gg + 1];
        int nt = (c1 - c0 + 127) >> 7;
        if (g < 0 && bid < acct + nt) { g = gg; row_start = c0 + (bid - acct) * 128; row_end = c1; }
        acct += nt;
    }
    if (g < 0) return;
    const int n0 = blockIdx.x * 128;

    extern __shared__ __align__(1024) char smem[];
    const uint32_t sbase = smem_u32(smem);
    const int tid = threadIdx.x, wid = tid >> 5, lane = tid & 31;
    const int wm = wid >> 1, wn = wid & 1;

    const __nv_bfloat16* WH = g_W1Th + (size_t)(g * DF + n0) * DIN;
    const __nv_bfloat16* WL = g_W1Tl + (size_t)(g * DF + n0) * DIN;
    const __nv_bfloat16* AH = g_sth + (size_t)row_start * DIN;
    const __nv_bfloat16* AL = g_stl + (size_t)row_start * DIN;
    const int seg = tid & 3, rt0 = tid >> 2;   // rt0 in 0..63

    float acc[2][8][4];
#pragma unroll
    for (int a = 0; a < 2; a++)
#pragma unroll
        for (int b = 0; b < 8; b++)
#pragma unroll
            for (int c = 0; c < 4; c++) acc[a][b][c] = 0.f;

    auto issue = [&](int c) {
        uint32_t sst = sbase + (uint32_t)(c % NSTAGE) * STAGE_B;
        const int k0 = c * 32;
#pragma unroll
        for (int it = 0; it < 2; it++) {
            int rt = rt0 + it * 64;
            size_t rb = (size_t)rt * DIN + k0 + seg * 8;
            uint32_t off = SWZ64((uint32_t)(rt * 64 + seg * 16));
            cp16(sst + OFF_AH + off, AH + rb);
            cp16(sst + OFF_AL + off, AL + rb);
        }
#pragma unroll
        for (int it = 0; it < 2; it++) {
            int rn = rt0 + it * 64;
            size_t rb = (size_t)rn * DIN + k0 + seg * 8;
            uint32_t off = SWZ64((uint32_t)(rn * 64 + seg * 16));
            cp16(sst + OFF_BH + off, WH + rb);
            cp16(sst + OFF_BL + off, WL + rb);
        }
        CP_COMMIT();
    };

    const int CH = DIN / 32;   // 16
    issue(0); issue(1);
    for (int c = 0; c < CH; c++) {
        if (c < CH - 1) {
            asm volatile("cp.async.wait_group 1;" ::: "memory");
        } else {
            asm volatile("cp.async.wait_group 0;" ::: "memory");
        }
        __syncthreads();
        if (c + 2 < CH) issue(c + 2);
        mma_chunk(sbase + (uint32_t)(c % NSTAGE) * STAGE_B, acc, wm, wn, lane);
    }

    // epilogue: bias + sigmoid + bf16 hi/lo split -> g_h1h/g_h1l
    const float* bb = b1 + g * DF + n0;
#pragma unroll
    for (int mi = 0; mi < 2; mi++) {
        int r1 = row_start + wm * 32 + mi * 16 + (lane >> 2);
        int r2 = r1 + 8;
#pragma unroll
        for (int nj = 0; nj < 8; nj++) {
            int n = wn * 64 + nj * 8 + (lane & 3) * 2;
            float* a = acc[mi][nj];
            if (r1 < row_end) {
                float s0 = 1.f / (1.f + __expf(-(a[0] + bb[n])));
                float s1 = 1.f / (1.f + __expf(-(a[1] + bb[n + 1])));
                float l0 = s0 - __bfloat162float(__float2bfloat16(s0));
                float l1 = s1 - __bfloat162float(__float2bfloat16(s1));
                *(uint32_t*)(g_h1h + (size_t)r1 * DF + n0 + n) = pack_bf2(s0, s1);
                *(uint32_t*)(g_h1l + (size_t)r1 * DF + n0 + n) = pack_bf2(l0, l1);
            }
            if (r2 < row_end) {
                float s0 = 1.f / (1.f + __expf(-(a[2] + bb[n])));
                float s1 = 1.f / (1.f + __expf(-(a[3] + bb[n + 1])));
                float l0 = s0 - __bfloat162float(__float2bfloat16(s0));
                float l1 = s1 - __bfloat162float(__float2bfloat16(s1));
                *(uint32_t*)(g_h1h + (size_t)r2 * DF + n0 + n) = pack_bf2(s0, s1);
                *(uint32_t*)(g_h1l + (size_t)r2 * DF + n0 + n) = pack_bf2(l0, l1);
            }
        }
    }
}

// ---------------- 4. GEMM2 + fused partial Q head ----------------------------
// grid (2, 512): N-tile fast dim for L2 reuse of h1 rows
__global__ void __launch_bounds__(256, 2) gemm2_mma(const float* __restrict__ b2,
                                                    const int* __restrict__ action,
                                                    const int* __restrict__ idx,
                                                    const float* __restrict__ Wq)
{
    const int m0 = blockIdx.y * 128;
    const int n0 = blockIdx.x * 128;
    extern __shared__ __align__(1024) char smem[];
    const uint32_t sbase = smem_u32(smem);
    const int tid = threadIdx.x, wid = tid >> 5, lane = tid & 31;
    const int wm = wid >> 1, wn = wid & 1;
    const int seg = tid & 3, rt0 = tid >> 2;

    const __nv_bfloat16* WH = g_W2Th + (size_t)n0 * DF;
    const __nv_bfloat16* WL = g_W2Tl + (size_t)n0 * DF;

    float acc[2][8][4];
#pragma unroll
    for (int a = 0; a < 2; a++)
#pragma unroll
        for (int b = 0; b < 8; b++)
#pragma unroll
            for (int c = 0; c < 4; c++) acc[a][b][c] = 0.f;

    auto issue = [&](int c) {
        uint32_t sst = sbase + (uint32_t)(c % NSTAGE) * STAGE_B;
        const int k0 = c * 32;
#pragma unroll
        for (int it = 0; it < 2; it++) {
            int rt = rt0 + it * 64;
            size_t rb = (size_t)(m0 + rt) * DF + k0 + seg * 8;
            uint32_t off = SWZ64((uint32_t)(rt * 64 + seg * 16));
            cp16(sst + OFF_AH + off, g_h1h + rb);
            cp16(sst + OFF_AL + off, g_h1l + rb);
        }
#pragma unroll
        for (int it = 0; it < 2; it++) {
            int rn = rt0 + it * 64;
            size_t rb = (size_t)rn * DF + k0 + seg * 8;
            uint32_t off = SWZ64((uint32_t)(rn * 64 + seg * 16));
            cp16(sst + OFF_BH + off, WH + rb);
            cp16(sst + OFF_BL + off, WL + rb);
        }
        CP_COMMIT();
    };

    const int CH = DF / 32;    // 8
    issue(0); issue(1);
    for (int c = 0; c < CH; c++) {
        if (c < CH - 1) {
            asm volatile("cp.async.wait_group 1;" ::: "memory");
        } else {
            asm volatile("cp.async.wait_group 0;" ::: "memory");
        }
        __syncthreads();
        if (c + 2 < CH) issue(c + 2);
        mma_chunk(sbase + (uint32_t)(c % NSTAGE) * STAGE_B, acc, wm, wn, lane);
    }

    // fused epilogue: partial dot of relu(acc + b2) with Wq[idx,:,action]
    const int slot = blockIdx.x * 2 + wn;      // 0..3
#pragma unroll
    for (int mi = 0; mi < 2; mi++) {
        const int rA = m0 + wm * 32 + mi * 16 + (lane >> 2);
        const int rB = rA + 8;
        const float* wqA = Wq + (size_t)idx[rA] * DF * NOUT + action[rA];
        const float* wqB = Wq + (size_t)idx[rB] * DF * NOUT + action[rB];
        float pA = 0.f, pB = 0.f;
#pragma unroll
        for (int nj = 0; nj < 8; nj++) {
            int n = n0 + wn * 64 + nj * 8 + (lane & 3) * 2;
            float* a = acc[mi][nj];
            float b20 = b2[n], b21 = b2[n + 1];
            pA += fmaxf(a[0] + b20, 0.f) * wqA[(size_t)n * NOUT]
                + fmaxf(a[1] + b21, 0.f) * wqA[(size_t)(n + 1) * NOUT];
            pB += fmaxf(a[2] + b20, 0.f) * wqB[(size_t)n * NOUT]
                + fmaxf(a[3] + b21, 0.f) * wqB[(size_t)(n + 1) * NOUT];
        }
        pA += __shfl_xor_sync(0xFFFFFFFFu, pA, 1);
        pA += __shfl_xor_sync(0xFFFFFFFFu, pA, 2);
        pB += __shfl_xor_sync(0xFFFFFFFFu, pB, 1);
        pB += __shfl_xor_sync(0xFFFFFFFFu, pB, 2);
        if ((lane & 3) == 0) {
            g_qpart[(size_t)rA * 4 + slot] = pA;
            g_qpart[(size_t)rB * 4 + slot] = pB;
        }
    }
}

// ---------------- 5. finish: sum partials + bias + tanh ----------------------
__global__ void __launch_bounds__(256) finishq(const int* __restrict__ action,
                                               const int* __restrict__ idx,
                                               const float* __restrict__ bq,
                                               float* __restrict__ out)
{
    const int m = blockIdx.x * 256 + threadIdx.x;
    float4 p = ((const float4*)g_qpart)[m];
    const int gi = idx[m];
    const int ai = action[m];
    out[m] = tanhf(p.x + p.y + p.z + p.w + bq[gi * NOUT + ai]);
}

// ---------------- launcher ---------------------------------------------------
extern "C" void kernel_launch(void* const* d_in, const int* in_sizes, int n_in,
                              void* d_out, int out_size)
{
    const float* state  = (const float*)d_in[0];
    const int*   action = (const int*)d_in[1];
    const int*   idx    = (const int*)d_in[2];
    const float* W1     = (const float*)d_in[3];
    const float* b1     = (const float*)d_in[4];
    const float* W2     = (const float*)d_in[5];
    const float* b2     = (const float*)d_in[6];
    const float* Wq     = (const float*)d_in[7];
    const float* bq     = (const float*)d_in[8];
    float* out = (float*)d_out;

    cudaFuncSetAttribute(gemm1_mma, cudaFuncAttributeMaxDynamicSharedMemorySize, SMEM_TOTAL);
    cudaFuncSetAttribute(gemm2_mma, cudaFuncAttributeMaxDynamicSharedMemorySize, SMEM_TOTAL);

    sort_count<<<64, 256>>>(idx);
    sort_scan<<<1, 32>>>();
    prep_weights<<<dim3(DIN / 32, DF / 32, NGRP + 1), 256>>>(W1, W2);
    sort_scatter<<<64, 256>>>(idx);
    prep_state<<<(BATCH * DIN / 8) / 256, 256>>>(state);
    gemm1_mma<<<dim3(2, 518), 256, SMEM_TOTAL>>>(b1);
    gemm2_mma<<<dim3(2, BATCH / 128), 256, SMEM_TOTAL>>>(b2, action, idx, Wq);
    finishq<<<BATCH / 256, 256>>>(action, idx, bq, out);
}